// round 11
// baseline (speedup 1.0000x reference)
#include <cuda_runtime.h>
#include <cuda_fp16.h>

#define D      128
#define EF     16
#define NMAX   50000
#define EMAX   1600000
#define NCHUNK_MAX 256   // ceil(NMAX/256) = 196 <= 256

typedef unsigned long long u64;

// ---------------- scratch (device globals; zero-init, no allocation) -------
__device__ float  g_pool[NMAX * D];    // e2n pooled edge messages
__device__ float  g_static[NMAX * D];  // e2n_pool @ W0 (pre-relu)
__device__ float  g_A[NMAX * D];       // static + h @ W1
__device__ __half g_Yh[NMAX * D];      // h @ W2, fp16
__device__ float  g_h[NMAX * D];       // hidden state

__device__ int g_cnt[2][NMAX];
__device__ int g_off[2][NMAX + 1];
__device__ int g_cur[2][NMAX];
__device__ int g_csum[2][NCHUNK_MAX];
__device__ int g_coff[2][NCHUNK_MAX];
__device__ int g_permA[EMAX];          // edge ids grouped by e2n_dst
__device__ int g_permB[EMAX];          // edge_src values grouped by edge_dst

// ---------------- f32x2 packed math helpers --------------------------------
__device__ __forceinline__ u64 pack2(float x) {
    unsigned int u = __float_as_uint(x);
    u64 r;
    asm("mov.b64 %0, {%1, %2};" : "=l"(r) : "r"(u), "r"(u));
    return r;
}
__device__ __forceinline__ u64 ffma2(u64 a, u64 b, u64 c) {
    u64 d;
    asm("fma.rn.f32x2 %0, %1, %2, %3;" : "=l"(d) : "l"(a), "l"(b), "l"(c));
    return d;
}
__device__ __forceinline__ float2 unpack2(u64 v) {
    unsigned int lo, hi;
    asm("mov.b64 {%0, %1}, %2;" : "=r"(lo), "=r"(hi) : "l"(v));
    return make_float2(__uint_as_float(lo), __uint_as_float(hi));
}
// sum the even-k / odd-k halves of an interleaved accumulator
__device__ __forceinline__ float acc_sum(u64 v) {
    float2 e = unpack2(v);
    return e.x + e.y;
}

// ---------------- CSR builders ---------------------------------------------
__global__ void k_zero_cnt(int n) {
    int i = blockIdx.x * blockDim.x + threadIdx.x;
    int s = gridDim.x * blockDim.x;
    for (; i < n; i += s) { g_cnt[0][i] = 0; g_cnt[1][i] = 0; }
}

__global__ void k_hist(const int* __restrict__ e2n, const int* __restrict__ ndst, int E) {
    int E4 = E >> 2;
    int i = blockIdx.x * blockDim.x + threadIdx.x;
    int s = gridDim.x * blockDim.x;
    for (; i < E4; i += s) {
        int4 a = ((const int4*)e2n)[i];
        int4 b = ((const int4*)ndst)[i];
        atomicAdd(&g_cnt[0][a.x], 1); atomicAdd(&g_cnt[0][a.y], 1);
        atomicAdd(&g_cnt[0][a.z], 1); atomicAdd(&g_cnt[0][a.w], 1);
        atomicAdd(&g_cnt[1][b.x], 1); atomicAdd(&g_cnt[1][b.y], 1);
        atomicAdd(&g_cnt[1][b.z], 1); atomicAdd(&g_cnt[1][b.w], 1);
    }
    int t = E4 * 4 + (blockIdx.x * blockDim.x + threadIdx.x);
    if (t < E) {
        atomicAdd(&g_cnt[0][e2n[t]], 1);
        atomicAdd(&g_cnt[1][ndst[t]], 1);
    }
}

__global__ void k_scan1(int n) {
    __shared__ int sh[256];
    int a = blockIdx.y;
    int i = blockIdx.x * 256 + threadIdx.x;
    sh[threadIdx.x] = (i < n) ? g_cnt[a][i] : 0;
    __syncthreads();
    for (int o = 128; o > 0; o >>= 1) {
        if (threadIdx.x < o) sh[threadIdx.x] += sh[threadIdx.x + o];
        __syncthreads();
    }
    if (threadIdx.x == 0) g_csum[a][blockIdx.x] = sh[0];
}

__global__ void k_scan2(int n, int nchunk) {
    __shared__ int sh[256];
    for (int a = 0; a < 2; a++) {
        int v = (threadIdx.x < nchunk) ? g_csum[a][threadIdx.x] : 0;
        sh[threadIdx.x] = v;
        __syncthreads();
        for (int o = 1; o < 256; o <<= 1) {
            int t = (threadIdx.x >= o) ? sh[threadIdx.x - o] : 0;
            __syncthreads();
            sh[threadIdx.x] += t;
            __syncthreads();
        }
        if (threadIdx.x < nchunk) g_coff[a][threadIdx.x] = sh[threadIdx.x] - v;
        if (threadIdx.x == 255)   g_off[a][n] = sh[255];
        __syncthreads();
    }
}

__global__ void k_scan3(int n) {
    __shared__ int sh[256];
    int a = blockIdx.y;
    int i = blockIdx.x * 256 + threadIdx.x;
    int v = (i < n) ? g_cnt[a][i] : 0;
    sh[threadIdx.x] = v;
    __syncthreads();
    for (int o = 1; o < 256; o <<= 1) {
        int t = (threadIdx.x >= o) ? sh[threadIdx.x - o] : 0;
        __syncthreads();
        sh[threadIdx.x] += t;
        __syncthreads();
    }
    if (i < n) {
        int excl = g_coff[a][blockIdx.x] + sh[threadIdx.x] - v;
        g_off[a][i] = excl;
        g_cur[a][i] = excl;
    }
}

__global__ void k_fill(const int* __restrict__ e2n, const int* __restrict__ ndst,
                       const int* __restrict__ nsrc, int E) {
    int E4 = E >> 2;
    int i = blockIdx.x * blockDim.x + threadIdx.x;
    int s = gridDim.x * blockDim.x;
    for (; i < E4; i += s) {
        int4 a = ((const int4*)e2n)[i];
        int4 b = ((const int4*)ndst)[i];
        int4 c = ((const int4*)nsrc)[i];
        int base = i * 4;
        int pa0 = atomicAdd(&g_cur[0][a.x], 1);
        int pa1 = atomicAdd(&g_cur[0][a.y], 1);
        int pa2 = atomicAdd(&g_cur[0][a.z], 1);
        int pa3 = atomicAdd(&g_cur[0][a.w], 1);
        int pb0 = atomicAdd(&g_cur[1][b.x], 1);
        int pb1 = atomicAdd(&g_cur[1][b.y], 1);
        int pb2 = atomicAdd(&g_cur[1][b.z], 1);
        int pb3 = atomicAdd(&g_cur[1][b.w], 1);
        g_permA[pa0] = base;     g_permA[pa1] = base + 1;
        g_permA[pa2] = base + 2; g_permA[pa3] = base + 3;
        g_permB[pb0] = c.x; g_permB[pb1] = c.y;
        g_permB[pb2] = c.z; g_permB[pb3] = c.w;
    }
    int t = E4 * 4 + (blockIdx.x * blockDim.x + threadIdx.x);
    if (t < E) {
        int pa = atomicAdd(&g_cur[0][e2n[t]], 1);
        g_permA[pa] = t;
        int pb = atomicAdd(&g_cur[1][ndst[t]], 1);
        g_permB[pb] = nsrc[t];
    }
}

// ---------------------------------------------------------------------------
// Per-node e2n pool. Weights in registers; edge loop unrolled x2. (R10-proven)
__global__ void __launch_bounds__(256) k_edge_pool(
    const float* __restrict__ ef, const float* __restrict__ We, int n)
{
    int lane = threadIdx.x & 31;
    int col  = lane * 4;

    ulonglong2 w[EF];
#pragma unroll
    for (int k = 0; k < EF; k++)
        w[k] = *(const ulonglong2*)(We + k * D + col);

    int gw = (blockIdx.x * blockDim.x + threadIdx.x) >> 5;
    int nw = (gridDim.x * blockDim.x) >> 5;

    for (int d = gw; d < n; d += nw) {
        int j0 = g_off[0][d], j1 = g_off[0][d + 1];
        float a0 = 0.f, a1 = 0.f, a2 = 0.f, a3 = 0.f;

        int j = j0;
        for (; j + 2 <= j1; j += 2) {
            int e0 = g_permA[j], e1 = g_permA[j + 1];
            float f0 = (lane < EF) ? ef[(size_t)e0 * EF + lane] : 0.f;
            float f1 = (lane < EF) ? ef[(size_t)e1 * EF + lane] : 0.f;
            u64 t00 = 0ull, t01 = 0ull, t10 = 0ull, t11 = 0ull;
#pragma unroll
            for (int k = 0; k < EF; k++) {
                u64 x0 = pack2(__shfl_sync(0xffffffffu, f0, k));
                u64 x1 = pack2(__shfl_sync(0xffffffffu, f1, k));
                t00 = ffma2(x0, w[k].x, t00);
                t01 = ffma2(x0, w[k].y, t01);
                t10 = ffma2(x1, w[k].x, t10);
                t11 = ffma2(x1, w[k].y, t11);
            }
            float2 p00 = unpack2(t00), p01 = unpack2(t01);
            float2 p10 = unpack2(t10), p11 = unpack2(t11);
            a0 += fmaxf(p00.x, 0.f) + fmaxf(p10.x, 0.f);
            a1 += fmaxf(p00.y, 0.f) + fmaxf(p10.y, 0.f);
            a2 += fmaxf(p01.x, 0.f) + fmaxf(p11.x, 0.f);
            a3 += fmaxf(p01.y, 0.f) + fmaxf(p11.y, 0.f);
        }
        if (j < j1) {
            int e0 = g_permA[j];
            float f0 = (lane < EF) ? ef[(size_t)e0 * EF + lane] : 0.f;
            u64 t00 = 0ull, t01 = 0ull;
#pragma unroll
            for (int k = 0; k < EF; k++) {
                u64 x0 = pack2(__shfl_sync(0xffffffffu, f0, k));
                t00 = ffma2(x0, w[k].x, t00);
                t01 = ffma2(x0, w[k].y, t01);
            }
            float2 p00 = unpack2(t00), p01 = unpack2(t01);
            a0 += fmaxf(p00.x, 0.f);
            a1 += fmaxf(p00.y, 0.f);
            a2 += fmaxf(p01.x, 0.f);
            a3 += fmaxf(p01.y, 0.f);
        }
        *(float4*)(g_pool + (size_t)d * D + col) = make_float4(a0, a1, a2, a3);
    }
}

// ---------------------------------------------------------------------------
// static = pool @ W0 ; h0 = relu(static).
// k-pair interleaved weights: sW[k2*D + c] = (W[2k2][c], W[2k2+1][c]) as u64.
// x loaded as natural LDS.64 pairs -> zero packing in the hot loop.
// 4 rows/warp; smem = 64KB weights + 16KB stage = 80KB -> 2 blocks/SM.
__global__ void __launch_bounds__(256) k_gemm_w0(const float* __restrict__ W, int n)
{
    extern __shared__ float sm[];
    u64*   sW    = (u64*)sm;          // D*D/2 u64 = 64 KB
    float* stage = sm + D * D;        // 8 warps * 4 rows * D floats = 16 KB

    for (int i = threadIdx.x; i < (D * D) / 2; i += blockDim.x) {
        int k2 = i >> 7;              // i / D
        int c  = i & (D - 1);         // i % D
        unsigned int lo = __float_as_uint(W[(2 * k2) * D + c]);
        unsigned int hi = __float_as_uint(W[(2 * k2 + 1) * D + c]);
        sW[i] = ((u64)hi << 32) | (u64)lo;
    }
    __syncthreads();

    int warp = threadIdx.x >> 5;
    int lane = threadIdx.x & 31;
    int col  = lane * 4;
    float* st = stage + warp * (4 * D);

    for (int r0 = blockIdx.x * 32 + warp * 4; r0 < n; r0 += gridDim.x * 32) {
        int rmax = n - r0; if (rmax > 4) rmax = 4;
#pragma unroll
        for (int rr = 0; rr < 4; rr++)
            if (rr < rmax)
                *(float4*)(st + rr * D + col) =
                    *(const float4*)(g_pool + (size_t)(r0 + rr) * D + col);
        __syncwarp();

        u64 acc[4][4];
#pragma unroll
        for (int rr = 0; rr < 4; rr++)
#pragma unroll
            for (int c4 = 0; c4 < 4; c4++) acc[rr][c4] = 0ull;

        for (int k2 = 0; k2 < D / 2; k2++) {
            ulonglong2 wA = *(const ulonglong2*)(sW + k2 * D + col);
            ulonglong2 wB = *(const ulonglong2*)(sW + k2 * D + col + 2);
#pragma unroll
            for (int rr = 0; rr < 4; rr++) {
                u64 x = *(const u64*)(st + rr * D + 2 * k2);
                acc[rr][0] = ffma2(x, wA.x, acc[rr][0]);
                acc[rr][1] = ffma2(x, wA.y, acc[rr][1]);
                acc[rr][2] = ffma2(x, wB.x, acc[rr][2]);
                acc[rr][3] = ffma2(x, wB.y, acc[rr][3]);
            }
        }
#pragma unroll
        for (int rr = 0; rr < 4; rr++) {
            if (rr < rmax) {
                float4 s = make_float4(acc_sum(acc[rr][0]), acc_sum(acc[rr][1]),
                                       acc_sum(acc[rr][2]), acc_sum(acc[rr][3]));
                *(float4*)(g_static + (size_t)(r0 + rr) * D + col) = s;
                *(float4*)(g_h + (size_t)(r0 + rr) * D + col) =
                    make_float4(fmaxf(s.x, 0.f), fmaxf(s.y, 0.f),
                                fmaxf(s.z, 0.f), fmaxf(s.w, 0.f));
            }
        }
        __syncwarp();
    }
}

// ---------------------------------------------------------------------------
// g_A = static + h @ W1 ; g_Yh = fp16(h @ W2). k-pair interleaved weights,
// 512 threads (4 warps/SMSP), 4 rows/warp.
// smem = 128KB weights + 32KB stage = 160KB -> 1 block/SM.
__global__ void __launch_bounds__(512) k_gemmAB(
    const float* __restrict__ W1, const float* __restrict__ W2, int n)
{
    extern __shared__ float sm[];
    u64*   sW1   = (u64*)sm;              // 64 KB
    u64*   sW2   = (u64*)(sm + D * D);    // 64 KB
    float* stage = sm + 2 * D * D;        // 16 warps * 4 * D floats = 32 KB

    for (int i = threadIdx.x; i < (D * D) / 2; i += blockDim.x) {
        int k2 = i >> 7;
        int c  = i & (D - 1);
        unsigned int lo1 = __float_as_uint(W1[(2 * k2) * D + c]);
        unsigned int hi1 = __float_as_uint(W1[(2 * k2 + 1) * D + c]);
        unsigned int lo2 = __float_as_uint(W2[(2 * k2) * D + c]);
        unsigned int hi2 = __float_as_uint(W2[(2 * k2 + 1) * D + c]);
        sW1[i] = ((u64)hi1 << 32) | (u64)lo1;
        sW2[i] = ((u64)hi2 << 32) | (u64)lo2;
    }
    __syncthreads();

    int warp = threadIdx.x >> 5;     // 0..15
    int lane = threadIdx.x & 31;
    int col  = lane * 4;
    float* st = stage + warp * (4 * D);

    for (int r0 = blockIdx.x * 64 + warp * 4; r0 < n; r0 += gridDim.x * 64) {
        int rmax = n - r0; if (rmax > 4) rmax = 4;
#pragma unroll
        for (int rr = 0; rr < 4; rr++)
            if (rr < rmax)
                *(float4*)(st + rr * D + col) =
                    *(const float4*)(g_h + (size_t)(r0 + rr) * D + col);
        __syncwarp();

        u64 a[4][4], y[4][4];
#pragma unroll
        for (int rr = 0; rr < 4; rr++)
#pragma unroll
            for (int c4 = 0; c4 < 4; c4++) { a[rr][c4] = 0ull; y[rr][c4] = 0ull; }

        for (int k2 = 0; k2 < D / 2; k2++) {
            ulonglong2 w1A = *(const ulonglong2*)(sW1 + k2 * D + col);
            ulonglong2 w1B = *(const ulonglong2*)(sW1 + k2 * D + col + 2);
            ulonglong2 w2A = *(const ulonglong2*)(sW2 + k2 * D + col);
            ulonglong2 w2B = *(const ulonglong2*)(sW2 + k2 * D + col + 2);
#pragma unroll
            for (int rr = 0; rr < 4; rr++) {
                u64 x = *(const u64*)(st + rr * D + 2 * k2);
                a[rr][0] = ffma2(x, w1A.x, a[rr][0]);
                a[rr][1] = ffma2(x, w1A.y, a[rr][1]);
                a[rr][2] = ffma2(x, w1B.x, a[rr][2]);
                a[rr][3] = ffma2(x, w1B.y, a[rr][3]);
                y[rr][0] = ffma2(x, w2A.x, y[rr][0]);
                y[rr][1] = ffma2(x, w2A.y, y[rr][1]);
                y[rr][2] = ffma2(x, w2B.x, y[rr][2]);
                y[rr][3] = ffma2(x, w2B.y, y[rr][3]);
            }
        }
#pragma unroll
        for (int rr = 0; rr < 4; rr++) {
            if (rr < rmax) {
                float4 s = *(const float4*)(g_static + (size_t)(r0 + rr) * D + col);
                float a0 = acc_sum(a[rr][0]), a1 = acc_sum(a[rr][1]);
                float a2 = acc_sum(a[rr][2]), a3 = acc_sum(a[rr][3]);
                float y0 = acc_sum(y[rr][0]), y1 = acc_sum(y[rr][1]);
                float y2 = acc_sum(y[rr][2]), y3 = acc_sum(y[rr][3]);
                *(float4*)(g_A + (size_t)(r0 + rr) * D + col) =
                    make_float4(s.x + a0, s.y + a1, s.z + a2, s.w + a3);
                __half2 q0 = __floats2half2_rn(y0, y1);
                __half2 q1 = __floats2half2_rn(y2, y3);
                uint2 pk;
                pk.x = *(unsigned int*)&q0;
                pk.y = *(unsigned int*)&q1;
                *(uint2*)(g_Yh + (size_t)(r0 + rr) * D + col) = pk;
            }
        }
        __syncwarp();
    }
}

// ---------------------------------------------------------------------------
// Fused n2n spmm + merge: out[d] = relu(A[d] + sum_{src in N(d)} Yh[src])
__global__ void __launch_bounds__(256) k_spmm_merge(float* __restrict__ out, int n)
{
    int lane = threadIdx.x & 31;
    int gw   = (blockIdx.x * blockDim.x + threadIdx.x) >> 5;
    int nw   = (gridDim.x * blockDim.x) >> 5;
    float* dst = out ? out : g_h;   // device-side select (host g_h addr invalid)
    int col  = lane * 4;

    for (int d = gw; d < n; d += nw) {
        int j0 = g_off[1][d], j1 = g_off[1][d + 1];
        float4 acc0 = *(const float4*)(g_A + (size_t)d * D + col);
        float4 acc1 = make_float4(0.f, 0.f, 0.f, 0.f);
        float4 acc2 = make_float4(0.f, 0.f, 0.f, 0.f);
        float4 acc3 = make_float4(0.f, 0.f, 0.f, 0.f);

        int j = j0;
        for (; j + 4 <= j1; j += 4) {
            int s0 = g_permB[j],     s1 = g_permB[j + 1];
            int s2 = g_permB[j + 2], s3 = g_permB[j + 3];
            uint2 r0 = *(const uint2*)(g_Yh + (size_t)s0 * D + col);
            uint2 r1 = *(const uint2*)(g_Yh + (size_t)s1 * D + col);
            uint2 r2 = *(const uint2*)(g_Yh + (size_t)s2 * D + col);
            uint2 r3 = *(const uint2*)(g_Yh + (size_t)s3 * D + col);
            float2 f0a = __half22float2(*(__half2*)&r0.x), f0b = __half22float2(*(__half2*)&r0.y);
            float2 f1a = __half22float2(*(__half2*)&r1.x), f1b = __half22float2(*(__half2*)&r1.y);
            float2 f2a = __half22float2(*(__half2*)&r2.x), f2b = __half22float2(*(__half2*)&r2.y);
            float2 f3a = __half22float2(*(__half2*)&r3.x), f3b = __half22float2(*(__half2*)&r3.y);
            acc0.x += f0a.x; acc0.y += f0a.y; acc0.z += f0b.x; acc0.w += f0b.y;
            acc1.x += f1a.x; acc1.y += f1a.y; acc1.z += f1b.x; acc1.w += f1b.y;
            acc2.x += f2a.x; acc2.y += f2a.y; acc2.z += f2b.x; acc2.w += f2b.y;
            acc3.x += f3a.x; acc3.y += f3a.y; acc3.z += f3b.x; acc3.w += f3b.y;
        }
        for (; j < j1; j++) {
            int s0 = g_permB[j];
            uint2 r0 = *(const uint2*)(g_Yh + (size_t)s0 * D + col);
            float2 f0a = __half22float2(*(__half2*)&r0.x), f0b = __half22float2(*(__half2*)&r0.y);
            acc0.x += f0a.x; acc0.y += f0a.y; acc0.z += f0b.x; acc0.w += f0b.y;
        }
        float4 o;
        o.x = fmaxf(acc0.x + acc1.x + acc2.x + acc3.x, 0.f);
        o.y = fmaxf(acc0.y + acc1.y + acc2.y + acc3.y, 0.f);
        o.z = fmaxf(acc0.z + acc1.z + acc2.z + acc3.z, 0.f);
        o.w = fmaxf(acc0.w + acc1.w + acc2.w + acc3.w, 0.f);
        *(float4*)(dst + (size_t)d * D + col) = o;
    }
}

// ---------------------------------------------------------------------------
extern "C" void kernel_launch(void* const* d_in, const int* in_sizes, int n_in,
                              void* d_out, int out_size)
{
    const float* edge_feat = (const float*)d_in[0];
    const float* W_e2l     = (const float*)d_in[1];
    const float* W0        = (const float*)d_in[2];
    const float* W1s[3] = { (const float*)d_in[3], (const float*)d_in[5], (const float*)d_in[7] };
    const float* W2s[3] = { (const float*)d_in[4], (const float*)d_in[6], (const float*)d_in[8] };
    const int* e2n_dst  = (const int*)d_in[9];
    const int* edge_src = (const int*)d_in[10];
    const int* edge_dst = (const int*)d_in[11];

    int E = in_sizes[9];
    int n = out_size / D;
    int nchunk = (n + 255) / 256;

    const int smem_w0 = (D * D + 8 * 4 * D) * (int)sizeof(float);          //  80 KB
    const int smem_ab = (2 * D * D + 16 * 4 * D) * (int)sizeof(float);     // 160 KB
    cudaFuncSetAttribute(k_gemm_w0, cudaFuncAttributeMaxDynamicSharedMemorySize, smem_w0);
    cudaFuncSetAttribute(k_gemmAB,  cudaFuncAttributeMaxDynamicSharedMemorySize, smem_ab);

    int node_blocks = (n + 7) / 8;     // warp per node
    int e4_blocks   = (E / 4 + 255) / 256;

    // --- CSR build ---
    k_zero_cnt<<<196, 256>>>(n);
    k_hist<<<e4_blocks, 256>>>(e2n_dst, edge_dst, E);
    dim3 sg(nchunk, 2);
    k_scan1<<<sg, 256>>>(n);
    k_scan2<<<1, 256>>>(n, nchunk);
    k_scan3<<<sg, 256>>>(n);
    k_fill<<<e4_blocks, 256>>>(e2n_dst, edge_dst, edge_src, E);

    // --- node pipeline ---
    k_edge_pool<<<node_blocks, 256>>>(edge_feat, W_e2l, n);
    k_gemm_w0<<<296, 256, smem_w0>>>(W0, n);

    for (int it = 0; it < 3; it++) {
        k_gemmAB<<<148, 512, smem_ab>>>(W1s[it], W2s[it], n);
        k_spmm_merge<<<node_blocks, 256>>>(it == 2 ? (float*)d_out : nullptr, n);
    }
}

// round 12
// speedup vs baseline: 1.1619x; 1.1619x over previous
#include <cuda_runtime.h>
#include <cuda_fp16.h>

#define D      128
#define EF     16
#define NMAX   50000
#define EMAX   1600000
#define NCHUNK_MAX 256   // ceil(NMAX/256) = 196 <= 256

typedef unsigned long long u64;

// ---------------- scratch (device globals; zero-init, no allocation) -------
__device__ float  g_pool[NMAX * D];    // e2n pooled edge messages
__device__ float  g_static[NMAX * D];  // e2n_pool @ W0 (pre-relu)
__device__ float  g_A[NMAX * D];       // static + h @ W1
__device__ __half g_Yh[NMAX * D];      // h @ W2, fp16
__device__ float  g_h[NMAX * D];       // hidden state

__device__ int g_cnt[2][NMAX];
__device__ int g_off[2][NMAX + 1];
__device__ int g_cur[2][NMAX];
__device__ int g_csum[2][NCHUNK_MAX];
__device__ int g_coff[2][NCHUNK_MAX];
__device__ int g_permA[EMAX];          // edge ids grouped by e2n_dst
__device__ int g_permB[EMAX];          // edge_src values grouped by edge_dst

// ---------------- f32x2 packed math helpers --------------------------------
__device__ __forceinline__ u64 pack2(float x) {
    unsigned int u = __float_as_uint(x);
    u64 r;
    asm("mov.b64 %0, {%1, %2};" : "=l"(r) : "r"(u), "r"(u));
    return r;
}
__device__ __forceinline__ u64 ffma2(u64 a, u64 b, u64 c) {
    u64 d;
    asm("fma.rn.f32x2 %0, %1, %2, %3;" : "=l"(d) : "l"(a), "l"(b), "l"(c));
    return d;
}
__device__ __forceinline__ float2 unpack2(u64 v) {
    unsigned int lo, hi;
    asm("mov.b64 {%0, %1}, %2;" : "=r"(lo), "=r"(hi) : "l"(v));
    return make_float2(__uint_as_float(lo), __uint_as_float(hi));
}

// ---------------- CSR builders ---------------------------------------------
__global__ void k_zero_cnt(int n) {
    int i = blockIdx.x * blockDim.x + threadIdx.x;
    int s = gridDim.x * blockDim.x;
    for (; i < n; i += s) { g_cnt[0][i] = 0; g_cnt[1][i] = 0; }
}

__global__ void k_hist(const int* __restrict__ e2n, const int* __restrict__ ndst, int E) {
    int E4 = E >> 2;
    int i = blockIdx.x * blockDim.x + threadIdx.x;
    int s = gridDim.x * blockDim.x;
    for (; i < E4; i += s) {
        int4 a = ((const int4*)e2n)[i];
        int4 b = ((const int4*)ndst)[i];
        atomicAdd(&g_cnt[0][a.x], 1); atomicAdd(&g_cnt[0][a.y], 1);
        atomicAdd(&g_cnt[0][a.z], 1); atomicAdd(&g_cnt[0][a.w], 1);
        atomicAdd(&g_cnt[1][b.x], 1); atomicAdd(&g_cnt[1][b.y], 1);
        atomicAdd(&g_cnt[1][b.z], 1); atomicAdd(&g_cnt[1][b.w], 1);
    }
    int t = E4 * 4 + (blockIdx.x * blockDim.x + threadIdx.x);
    if (t < E) {
        atomicAdd(&g_cnt[0][e2n[t]], 1);
        atomicAdd(&g_cnt[1][ndst[t]], 1);
    }
}

__global__ void k_scan1(int n) {
    __shared__ int sh[256];
    int a = blockIdx.y;
    int i = blockIdx.x * 256 + threadIdx.x;
    sh[threadIdx.x] = (i < n) ? g_cnt[a][i] : 0;
    __syncthreads();
    for (int o = 128; o > 0; o >>= 1) {
        if (threadIdx.x < o) sh[threadIdx.x] += sh[threadIdx.x + o];
        __syncthreads();
    }
    if (threadIdx.x == 0) g_csum[a][blockIdx.x] = sh[0];
}

__global__ void k_scan2(int n, int nchunk) {
    __shared__ int sh[256];
    for (int a = 0; a < 2; a++) {
        int v = (threadIdx.x < nchunk) ? g_csum[a][threadIdx.x] : 0;
        sh[threadIdx.x] = v;
        __syncthreads();
        for (int o = 1; o < 256; o <<= 1) {
            int t = (threadIdx.x >= o) ? sh[threadIdx.x - o] : 0;
            __syncthreads();
            sh[threadIdx.x] += t;
            __syncthreads();
        }
        if (threadIdx.x < nchunk) g_coff[a][threadIdx.x] = sh[threadIdx.x] - v;
        if (threadIdx.x == 255)   g_off[a][n] = sh[255];
        __syncthreads();
    }
}

__global__ void k_scan3(int n) {
    __shared__ int sh[256];
    int a = blockIdx.y;
    int i = blockIdx.x * 256 + threadIdx.x;
    int v = (i < n) ? g_cnt[a][i] : 0;
    sh[threadIdx.x] = v;
    __syncthreads();
    for (int o = 1; o < 256; o <<= 1) {
        int t = (threadIdx.x >= o) ? sh[threadIdx.x - o] : 0;
        __syncthreads();
        sh[threadIdx.x] += t;
        __syncthreads();
    }
    if (i < n) {
        int excl = g_coff[a][blockIdx.x] + sh[threadIdx.x] - v;
        g_off[a][i] = excl;
        g_cur[a][i] = excl;
    }
}

__global__ void k_fill(const int* __restrict__ e2n, const int* __restrict__ ndst,
                       const int* __restrict__ nsrc, int E) {
    int E4 = E >> 2;
    int i = blockIdx.x * blockDim.x + threadIdx.x;
    int s = gridDim.x * blockDim.x;
    for (; i < E4; i += s) {
        int4 a = ((const int4*)e2n)[i];
        int4 b = ((const int4*)ndst)[i];
        int4 c = ((const int4*)nsrc)[i];
        int base = i * 4;
        int pa0 = atomicAdd(&g_cur[0][a.x], 1);
        int pa1 = atomicAdd(&g_cur[0][a.y], 1);
        int pa2 = atomicAdd(&g_cur[0][a.z], 1);
        int pa3 = atomicAdd(&g_cur[0][a.w], 1);
        int pb0 = atomicAdd(&g_cur[1][b.x], 1);
        int pb1 = atomicAdd(&g_cur[1][b.y], 1);
        int pb2 = atomicAdd(&g_cur[1][b.z], 1);
        int pb3 = atomicAdd(&g_cur[1][b.w], 1);
        g_permA[pa0] = base;     g_permA[pa1] = base + 1;
        g_permA[pa2] = base + 2; g_permA[pa3] = base + 3;
        g_permB[pb0] = c.x; g_permB[pb1] = c.y;
        g_permB[pb2] = c.z; g_permB[pb3] = c.w;
    }
    int t = E4 * 4 + (blockIdx.x * blockDim.x + threadIdx.x);
    if (t < E) {
        int pa = atomicAdd(&g_cur[0][e2n[t]], 1);
        g_permA[pa] = t;
        int pb = atomicAdd(&g_cur[1][ndst[t]], 1);
        g_permB[pb] = nsrc[t];
    }
}

// ---------------------------------------------------------------------------
// Per-node e2n pool. Weights in registers; edge loop unrolled x2. (R10-proven)
__global__ void __launch_bounds__(256) k_edge_pool(
    const float* __restrict__ ef, const float* __restrict__ We, int n)
{
    int lane = threadIdx.x & 31;
    int col  = lane * 4;

    ulonglong2 w[EF];
#pragma unroll
    for (int k = 0; k < EF; k++)
        w[k] = *(const ulonglong2*)(We + k * D + col);

    int gw = (blockIdx.x * blockDim.x + threadIdx.x) >> 5;
    int nw = (gridDim.x * blockDim.x) >> 5;

    for (int d = gw; d < n; d += nw) {
        int j0 = g_off[0][d], j1 = g_off[0][d + 1];
        float a0 = 0.f, a1 = 0.f, a2 = 0.f, a3 = 0.f;

        int j = j0;
        for (; j + 2 <= j1; j += 2) {
            int e0 = g_permA[j], e1 = g_permA[j + 1];
            float f0 = (lane < EF) ? ef[(size_t)e0 * EF + lane] : 0.f;
            float f1 = (lane < EF) ? ef[(size_t)e1 * EF + lane] : 0.f;
            u64 t00 = 0ull, t01 = 0ull, t10 = 0ull, t11 = 0ull;
#pragma unroll
            for (int k = 0; k < EF; k++) {
                u64 x0 = pack2(__shfl_sync(0xffffffffu, f0, k));
                u64 x1 = pack2(__shfl_sync(0xffffffffu, f1, k));
                t00 = ffma2(x0, w[k].x, t00);
                t01 = ffma2(x0, w[k].y, t01);
                t10 = ffma2(x1, w[k].x, t10);
                t11 = ffma2(x1, w[k].y, t11);
            }
            float2 p00 = unpack2(t00), p01 = unpack2(t01);
            float2 p10 = unpack2(t10), p11 = unpack2(t11);
            a0 += fmaxf(p00.x, 0.f) + fmaxf(p10.x, 0.f);
            a1 += fmaxf(p00.y, 0.f) + fmaxf(p10.y, 0.f);
            a2 += fmaxf(p01.x, 0.f) + fmaxf(p11.x, 0.f);
            a3 += fmaxf(p01.y, 0.f) + fmaxf(p11.y, 0.f);
        }
        if (j < j1) {
            int e0 = g_permA[j];
            float f0 = (lane < EF) ? ef[(size_t)e0 * EF + lane] : 0.f;
            u64 t00 = 0ull, t01 = 0ull;
#pragma unroll
            for (int k = 0; k < EF; k++) {
                u64 x0 = pack2(__shfl_sync(0xffffffffu, f0, k));
                t00 = ffma2(x0, w[k].x, t00);
                t01 = ffma2(x0, w[k].y, t01);
            }
            float2 p00 = unpack2(t00), p01 = unpack2(t01);
            a0 += fmaxf(p00.x, 0.f);
            a1 += fmaxf(p00.y, 0.f);
            a2 += fmaxf(p01.x, 0.f);
            a3 += fmaxf(p01.y, 0.f);
        }
        *(float4*)(g_pool + (size_t)d * D + col) = make_float4(a0, a1, a2, a3);
    }
}

// ---------------------------------------------------------------------------
// static = pool @ W0 ; h0 = relu(static). R10 structure (8 rows/warp, float4
// stage, 96KB -> 2 blocks/SM), k-loop reads x as LDS64 pairs.
__global__ void __launch_bounds__(256) k_gemm_w0(const float* __restrict__ W, int n)
{
    extern __shared__ float sm[];
    float* sW    = sm;            // 64 KB
    float* stage = sm + D * D;    // 8*8*D*4 = 32 KB

    for (int i = threadIdx.x; i < D * D; i += blockDim.x) sW[i] = W[i];
    __syncthreads();

    int warp = threadIdx.x >> 5;
    int lane = threadIdx.x & 31;
    int col  = lane * 4;
    float* st = stage + warp * (8 * D);

    for (int r0 = blockIdx.x * 64 + warp * 8; r0 < n; r0 += gridDim.x * 64) {
        int rmax = n - r0; if (rmax > 8) rmax = 8;
#pragma unroll
        for (int rr = 0; rr < 8; rr++)
            if (rr < rmax)
                *(float4*)(st + rr * D + col) =
                    *(const float4*)(g_pool + (size_t)(r0 + rr) * D + col);
        __syncwarp();

        u64 a0[8], a1[8];
#pragma unroll
        for (int rr = 0; rr < 8; rr++) { a0[rr] = 0ull; a1[rr] = 0ull; }

        for (int k2 = 0; k2 < D / 2; k2++) {
            ulonglong2 we = *(const ulonglong2*)(sW + (2 * k2) * D + col);
            ulonglong2 wo = *(const ulonglong2*)(sW + (2 * k2 + 1) * D + col);
#pragma unroll
            for (int rr = 0; rr < 8; rr++) {
                u64 xp = *(const u64*)(st + rr * D + 2 * k2);   // LDS64 broadcast
                float2 xf = unpack2(xp);
                u64 xe = pack2(xf.x);
                u64 xo = pack2(xf.y);
                a0[rr] = ffma2(xe, we.x, a0[rr]);
                a1[rr] = ffma2(xe, we.y, a1[rr]);
                a0[rr] = ffma2(xo, wo.x, a0[rr]);
                a1[rr] = ffma2(xo, wo.y, a1[rr]);
            }
        }
#pragma unroll
        for (int rr = 0; rr < 8; rr++) {
            if (rr < rmax) {
                float2 p0 = unpack2(a0[rr]), p1 = unpack2(a1[rr]);
                float4 s = make_float4(p0.x, p0.y, p1.x, p1.y);
                *(float4*)(g_static + (size_t)(r0 + rr) * D + col) = s;
                *(float4*)(g_h + (size_t)(r0 + rr) * D + col) =
                    make_float4(fmaxf(s.x, 0.f), fmaxf(s.y, 0.f),
                                fmaxf(s.z, 0.f), fmaxf(s.w, 0.f));
            }
        }
        __syncwarp();
    }
}

// ---------------------------------------------------------------------------
// g_A = static + h @ W1 ; g_Yh = fp16(h @ W2).
// R10 structure (512 threads, 8 rows/warp, 192KB), k-loop reads x via LDS64.
__global__ void __launch_bounds__(512) k_gemmAB(
    const float* __restrict__ W1, const float* __restrict__ W2, int n)
{
    extern __shared__ float sm[];
    float* sW1   = sm;                // 64 KB
    float* sW2   = sm + D * D;        // 64 KB
    float* stage = sm + 2 * D * D;    // 16*8*D*4 = 64 KB

    for (int i = threadIdx.x; i < D * D; i += blockDim.x) {
        sW1[i] = W1[i];
        sW2[i] = W2[i];
    }
    __syncthreads();

    int warp = threadIdx.x >> 5;     // 0..15
    int lane = threadIdx.x & 31;
    int col  = lane * 4;
    float* st = stage + warp * (8 * D);

    for (int r0 = blockIdx.x * 128 + warp * 8; r0 < n; r0 += gridDim.x * 128) {
        int rmax = n - r0; if (rmax > 8) rmax = 8;
#pragma unroll
        for (int rr = 0; rr < 8; rr++)
            if (rr < rmax)
                *(float4*)(st + rr * D + col) =
                    *(const float4*)(g_h + (size_t)(r0 + rr) * D + col);
        __syncwarp();

        u64 a0[8], a1[8], y0[8], y1[8];
#pragma unroll
        for (int rr = 0; rr < 8; rr++) {
            a0[rr] = 0ull; a1[rr] = 0ull; y0[rr] = 0ull; y1[rr] = 0ull;
        }

        for (int k2 = 0; k2 < D / 2; k2++) {
            ulonglong2 w1e = *(const ulonglong2*)(sW1 + (2 * k2) * D + col);
            ulonglong2 w1o = *(const ulonglong2*)(sW1 + (2 * k2 + 1) * D + col);
            ulonglong2 w2e = *(const ulonglong2*)(sW2 + (2 * k2) * D + col);
            ulonglong2 w2o = *(const ulonglong2*)(sW2 + (2 * k2 + 1) * D + col);
#pragma unroll
            for (int rr = 0; rr < 8; rr++) {
                u64 xp = *(const u64*)(st + rr * D + 2 * k2);   // LDS64 broadcast
                float2 xf = unpack2(xp);
                u64 xe = pack2(xf.x);
                u64 xo = pack2(xf.y);
                a0[rr] = ffma2(xe, w1e.x, a0[rr]);
                a1[rr] = ffma2(xe, w1e.y, a1[rr]);
                y0[rr] = ffma2(xe, w2e.x, y0[rr]);
                y1[rr] = ffma2(xe, w2e.y, y1[rr]);
                a0[rr] = ffma2(xo, w1o.x, a0[rr]);
                a1[rr] = ffma2(xo, w1o.y, a1[rr]);
                y0[rr] = ffma2(xo, w2o.x, y0[rr]);
                y1[rr] = ffma2(xo, w2o.y, y1[rr]);
            }
        }
#pragma unroll
        for (int rr = 0; rr < 8; rr++) {
            if (rr < rmax) {
                float4 s = *(const float4*)(g_static + (size_t)(r0 + rr) * D + col);
                float2 pa0 = unpack2(a0[rr]), pa1 = unpack2(a1[rr]);
                float2 py0 = unpack2(y0[rr]), py1 = unpack2(y1[rr]);
                *(float4*)(g_A + (size_t)(r0 + rr) * D + col) =
                    make_float4(s.x + pa0.x, s.y + pa0.y, s.z + pa1.x, s.w + pa1.y);
                __half2 q0 = __floats2half2_rn(py0.x, py0.y);
                __half2 q1 = __floats2half2_rn(py1.x, py1.y);
                uint2 pk;
                pk.x = *(unsigned int*)&q0;
                pk.y = *(unsigned int*)&q1;
                *(uint2*)(g_Yh + (size_t)(r0 + rr) * D + col) = pk;
            }
        }
        __syncwarp();
    }
}

// ---------------------------------------------------------------------------
// Fused n2n spmm + merge: out[d] = relu(A[d] + sum_{src in N(d)} Yh[src])
__global__ void __launch_bounds__(256) k_spmm_merge(float* __restrict__ out, int n)
{
    int lane = threadIdx.x & 31;
    int gw   = (blockIdx.x * blockDim.x + threadIdx.x) >> 5;
    int nw   = (gridDim.x * blockDim.x) >> 5;
    float* dst = out ? out : g_h;   // device-side select (host g_h addr invalid)
    int col  = lane * 4;

    for (int d = gw; d < n; d += nw) {
        int j0 = g_off[1][d], j1 = g_off[1][d + 1];
        float4 acc0 = *(const float4*)(g_A + (size_t)d * D + col);
        float4 acc1 = make_float4(0.f, 0.f, 0.f, 0.f);
        float4 acc2 = make_float4(0.f, 0.f, 0.f, 0.f);
        float4 acc3 = make_float4(0.f, 0.f, 0.f, 0.f);

        int j = j0;
        for (; j + 4 <= j1; j += 4) {
            int s0 = g_permB[j],     s1 = g_permB[j + 1];
            int s2 = g_permB[j + 2], s3 = g_permB[j + 3];
            uint2 r0 = *(const uint2*)(g_Yh + (size_t)s0 * D + col);
            uint2 r1 = *(const uint2*)(g_Yh + (size_t)s1 * D + col);
            uint2 r2 = *(const uint2*)(g_Yh + (size_t)s2 * D + col);
            uint2 r3 = *(const uint2*)(g_Yh + (size_t)s3 * D + col);
            float2 f0a = __half22float2(*(__half2*)&r0.x), f0b = __half22float2(*(__half2*)&r0.y);
            float2 f1a = __half22float2(*(__half2*)&r1.x), f1b = __half22float2(*(__half2*)&r1.y);
            float2 f2a = __half22float2(*(__half2*)&r2.x), f2b = __half22float2(*(__half2*)&r2.y);
            float2 f3a = __half22float2(*(__half2*)&r3.x), f3b = __half22float2(*(__half2*)&r3.y);
            acc0.x += f0a.x; acc0.y += f0a.y; acc0.z += f0b.x; acc0.w += f0b.y;
            acc1.x += f1a.x; acc1.y += f1a.y; acc1.z += f1b.x; acc1.w += f1b.y;
            acc2.x += f2a.x; acc2.y += f2a.y; acc2.z += f2b.x; acc2.w += f2b.y;
            acc3.x += f3a.x; acc3.y += f3a.y; acc3.z += f3b.x; acc3.w += f3b.y;
        }
        for (; j < j1; j++) {
            int s0 = g_permB[j];
            uint2 r0 = *(const uint2*)(g_Yh + (size_t)s0 * D + col);
            float2 f0a = __half22float2(*(__half2*)&r0.x), f0b = __half22float2(*(__half2*)&r0.y);
            acc0.x += f0a.x; acc0.y += f0a.y; acc0.z += f0b.x; acc0.w += f0b.y;
        }
        float4 o;
        o.x = fmaxf(acc0.x + acc1.x + acc2.x + acc3.x, 0.f);
        o.y = fmaxf(acc0.y + acc1.y + acc2.y + acc3.y, 0.f);
        o.z = fmaxf(acc0.z + acc1.z + acc2.z + acc3.z, 0.f);
        o.w = fmaxf(acc0.w + acc1.w + acc2.w + acc3.w, 0.f);
        *(float4*)(dst + (size_t)d * D + col) = o;
    }
}

// ---------------------------------------------------------------------------
extern "C" void kernel_launch(void* const* d_in, const int* in_sizes, int n_in,
                              void* d_out, int out_size)
{
    const float* edge_feat = (const float*)d_in[0];
    const float* W_e2l     = (const float*)d_in[1];
    const float* W0        = (const float*)d_in[2];
    const float* W1s[3] = { (const float*)d_in[3], (const float*)d_in[5], (const float*)d_in[7] };
    const float* W2s[3] = { (const float*)d_in[4], (const float*)d_in[6], (const float*)d_in[8] };
    const int* e2n_dst  = (const int*)d_in[9];
    const int* edge_src = (const int*)d_in[10];
    const int* edge_dst = (const int*)d_in[11];

    int E = in_sizes[9];
    int n = out_size / D;
    int nchunk = (n + 255) / 256;

    const int smem_w0 = (D * D + 8 * 8 * D) * (int)sizeof(float);          //  96 KB
    const int smem_ab = (2 * D * D + 16 * 8 * D) * (int)sizeof(float);     // 192 KB
    cudaFuncSetAttribute(k_gemm_w0, cudaFuncAttributeMaxDynamicSharedMemorySize, smem_w0);
    cudaFuncSetAttribute(k_gemmAB,  cudaFuncAttributeMaxDynamicSharedMemorySize, smem_ab);

    int node_blocks = (n + 7) / 8;     // warp per node
    int e4_blocks   = (E / 4 + 255) / 256;

    // --- CSR build ---
    k_zero_cnt<<<196, 256>>>(n);
    k_hist<<<e4_blocks, 256>>>(e2n_dst, edge_dst, E);
    dim3 sg(nchunk, 2);
    k_scan1<<<sg, 256>>>(n);
    k_scan2<<<1, 256>>>(n, nchunk);
    k_scan3<<<sg, 256>>>(n);
    k_fill<<<e4_blocks, 256>>>(e2n_dst, edge_dst, edge_src, E);

    // --- node pipeline ---
    k_edge_pool<<<node_blocks, 256>>>(edge_feat, W_e2l, n);
    k_gemm_w0<<<296, 256, smem_w0>>>(W0, n);

    for (int it = 0; it < 3; it++) {
        k_gemmAB<<<148, 512, smem_ab>>>(W1s[it], W2s[it], n);
        k_spmm_merge<<<node_blocks, 256>>>(it == 2 ? (float*)d_out : nullptr, n);
    }
}

// round 13
// speedup vs baseline: 1.3457x; 1.1583x over previous
#include <cuda_runtime.h>
#include <cuda_fp16.h>
#include <mma.h>

using namespace nvcuda;

#define D      128
#define EF     16
#define NMAX   50000
#define EMAX   1600000
#define NCHUNK_MAX 256   // ceil(NMAX/256) = 196 <= 256

typedef unsigned long long u64;

// wmma staging leading dims (padded to dodge bank conflicts)
#define LDX 136      // fp16 X stage:    64 x 136
#define LDW 264      // fp16 W1|W2:     128 x 264 (cols 0..127 = W1, 128..255 = W2)
#define LDC 264      // fp32 C stage:    64 x 264

// ---------------- scratch (device globals; zero-init, no allocation) -------
__device__ float  g_pool[NMAX * D];    // e2n pooled edge messages
__device__ float  g_static[NMAX * D];  // e2n_pool @ W0 (pre-relu)
__device__ float  g_A[NMAX * D];       // static + h @ W1
__device__ __half g_Yh[NMAX * D];      // h @ W2, fp16
__device__ float  g_h[NMAX * D];       // hidden state

__device__ int g_cnt[2][NMAX];
__device__ int g_off[2][NMAX + 1];
__device__ int g_cur[2][NMAX];
__device__ int g_csum[2][NCHUNK_MAX];
__device__ int g_coff[2][NCHUNK_MAX];
__device__ int g_permA[EMAX];          // edge ids grouped by e2n_dst
__device__ int g_permB[EMAX];          // edge_src values grouped by edge_dst

// ---------------- f32x2 packed math helpers --------------------------------
__device__ __forceinline__ u64 pack2(float x) {
    unsigned int u = __float_as_uint(x);
    u64 r;
    asm("mov.b64 %0, {%1, %2};" : "=l"(r) : "r"(u), "r"(u));
    return r;
}
__device__ __forceinline__ u64 ffma2(u64 a, u64 b, u64 c) {
    u64 d;
    asm("fma.rn.f32x2 %0, %1, %2, %3;" : "=l"(d) : "l"(a), "l"(b), "l"(c));
    return d;
}
__device__ __forceinline__ float2 unpack2(u64 v) {
    unsigned int lo, hi;
    asm("mov.b64 {%0, %1}, %2;" : "=r"(lo), "=r"(hi) : "l"(v));
    return make_float2(__uint_as_float(lo), __uint_as_float(hi));
}

// ---------------- CSR builders ---------------------------------------------
__global__ void k_zero_cnt(int n) {
    int i = blockIdx.x * blockDim.x + threadIdx.x;
    int s = gridDim.x * blockDim.x;
    for (; i < n; i += s) { g_cnt[0][i] = 0; g_cnt[1][i] = 0; }
}

__global__ void k_hist(const int* __restrict__ e2n, const int* __restrict__ ndst, int E) {
    int E4 = E >> 2;
    int i = blockIdx.x * blockDim.x + threadIdx.x;
    int s = gridDim.x * blockDim.x;
    for (; i < E4; i += s) {
        int4 a = ((const int4*)e2n)[i];
        int4 b = ((const int4*)ndst)[i];
        atomicAdd(&g_cnt[0][a.x], 1); atomicAdd(&g_cnt[0][a.y], 1);
        atomicAdd(&g_cnt[0][a.z], 1); atomicAdd(&g_cnt[0][a.w], 1);
        atomicAdd(&g_cnt[1][b.x], 1); atomicAdd(&g_cnt[1][b.y], 1);
        atomicAdd(&g_cnt[1][b.z], 1); atomicAdd(&g_cnt[1][b.w], 1);
    }
    int t = E4 * 4 + (blockIdx.x * blockDim.x + threadIdx.x);
    if (t < E) {
        atomicAdd(&g_cnt[0][e2n[t]], 1);
        atomicAdd(&g_cnt[1][ndst[t]], 1);
    }
}

__global__ void k_scan1(int n) {
    __shared__ int sh[256];
    int a = blockIdx.y;
    int i = blockIdx.x * 256 + threadIdx.x;
    sh[threadIdx.x] = (i < n) ? g_cnt[a][i] : 0;
    __syncthreads();
    for (int o = 128; o > 0; o >>= 1) {
        if (threadIdx.x < o) sh[threadIdx.x] += sh[threadIdx.x + o];
        __syncthreads();
    }
    if (threadIdx.x == 0) g_csum[a][blockIdx.x] = sh[0];
}

__global__ void k_scan2(int n, int nchunk) {
    __shared__ int sh[256];
    for (int a = 0; a < 2; a++) {
        int v = (threadIdx.x < nchunk) ? g_csum[a][threadIdx.x] : 0;
        sh[threadIdx.x] = v;
        __syncthreads();
        for (int o = 1; o < 256; o <<= 1) {
            int t = (threadIdx.x >= o) ? sh[threadIdx.x - o] : 0;
            __syncthreads();
            sh[threadIdx.x] += t;
            __syncthreads();
        }
        if (threadIdx.x < nchunk) g_coff[a][threadIdx.x] = sh[threadIdx.x] - v;
        if (threadIdx.x == 255)   g_off[a][n] = sh[255];
        __syncthreads();
    }
}

__global__ void k_scan3(int n) {
    __shared__ int sh[256];
    int a = blockIdx.y;
    int i = blockIdx.x * 256 + threadIdx.x;
    int v = (i < n) ? g_cnt[a][i] : 0;
    sh[threadIdx.x] = v;
    __syncthreads();
    for (int o = 1; o < 256; o <<= 1) {
        int t = (threadIdx.x >= o) ? sh[threadIdx.x - o] : 0;
        __syncthreads();
        sh[threadIdx.x] += t;
        __syncthreads();
    }
    if (i < n) {
        int excl = g_coff[a][blockIdx.x] + sh[threadIdx.x] - v;
        g_off[a][i] = excl;
        g_cur[a][i] = excl;
    }
}

__global__ void k_fill(const int* __restrict__ e2n, const int* __restrict__ ndst,
                       const int* __restrict__ nsrc, int E) {
    int E4 = E >> 2;
    int i = blockIdx.x * blockDim.x + threadIdx.x;
    int s = gridDim.x * blockDim.x;
    for (; i < E4; i += s) {
        int4 a = ((const int4*)e2n)[i];
        int4 b = ((const int4*)ndst)[i];
        int4 c = ((const int4*)nsrc)[i];
        int base = i * 4;
        int pa0 = atomicAdd(&g_cur[0][a.x], 1);
        int pa1 = atomicAdd(&g_cur[0][a.y], 1);
        int pa2 = atomicAdd(&g_cur[0][a.z], 1);
        int pa3 = atomicAdd(&g_cur[0][a.w], 1);
        int pb0 = atomicAdd(&g_cur[1][b.x], 1);
        int pb1 = atomicAdd(&g_cur[1][b.y], 1);
        int pb2 = atomicAdd(&g_cur[1][b.z], 1);
        int pb3 = atomicAdd(&g_cur[1][b.w], 1);
        g_permA[pa0] = base;     g_permA[pa1] = base + 1;
        g_permA[pa2] = base + 2; g_permA[pa3] = base + 3;
        g_permB[pb0] = c.x; g_permB[pb1] = c.y;
        g_permB[pb2] = c.z; g_permB[pb3] = c.w;
    }
    int t = E4 * 4 + (blockIdx.x * blockDim.x + threadIdx.x);
    if (t < E) {
        int pa = atomicAdd(&g_cur[0][e2n[t]], 1);
        g_permA[pa] = t;
        int pb = atomicAdd(&g_cur[1][ndst[t]], 1);
        g_permB[pb] = nsrc[t];
    }
}

// ---------------------------------------------------------------------------
// Per-node e2n pool. Weights in registers; edge loop unrolled x2. (R10-proven)
__global__ void __launch_bounds__(256) k_edge_pool(
    const float* __restrict__ ef, const float* __restrict__ We, int n)
{
    int lane = threadIdx.x & 31;
    int col  = lane * 4;

    ulonglong2 w[EF];
#pragma unroll
    for (int k = 0; k < EF; k++)
        w[k] = *(const ulonglong2*)(We + k * D + col);

    int gw = (blockIdx.x * blockDim.x + threadIdx.x) >> 5;
    int nw = (gridDim.x * blockDim.x) >> 5;

    for (int d = gw; d < n; d += nw) {
        int j0 = g_off[0][d], j1 = g_off[0][d + 1];
        float a0 = 0.f, a1 = 0.f, a2 = 0.f, a3 = 0.f;

        int j = j0;
        for (; j + 2 <= j1; j += 2) {
            int e0 = g_permA[j], e1 = g_permA[j + 1];
            float f0 = (lane < EF) ? ef[(size_t)e0 * EF + lane] : 0.f;
            float f1 = (lane < EF) ? ef[(size_t)e1 * EF + lane] : 0.f;
            u64 t00 = 0ull, t01 = 0ull, t10 = 0ull, t11 = 0ull;
#pragma unroll
            for (int k = 0; k < EF; k++) {
                u64 x0 = pack2(__shfl_sync(0xffffffffu, f0, k));
                u64 x1 = pack2(__shfl_sync(0xffffffffu, f1, k));
                t00 = ffma2(x0, w[k].x, t00);
                t01 = ffma2(x0, w[k].y, t01);
                t10 = ffma2(x1, w[k].x, t10);
                t11 = ffma2(x1, w[k].y, t11);
            }
            float2 p00 = unpack2(t00), p01 = unpack2(t01);
            float2 p10 = unpack2(t10), p11 = unpack2(t11);
            a0 += fmaxf(p00.x, 0.f) + fmaxf(p10.x, 0.f);
            a1 += fmaxf(p00.y, 0.f) + fmaxf(p10.y, 0.f);
            a2 += fmaxf(p01.x, 0.f) + fmaxf(p11.x, 0.f);
            a3 += fmaxf(p01.y, 0.f) + fmaxf(p11.y, 0.f);
        }
        if (j < j1) {
            int e0 = g_permA[j];
            float f0 = (lane < EF) ? ef[(size_t)e0 * EF + lane] : 0.f;
            u64 t00 = 0ull, t01 = 0ull;
#pragma unroll
            for (int k = 0; k < EF; k++) {
                u64 x0 = pack2(__shfl_sync(0xffffffffu, f0, k));
                t00 = ffma2(x0, w[k].x, t00);
                t01 = ffma2(x0, w[k].y, t01);
            }
            float2 p00 = unpack2(t00), p01 = unpack2(t01);
            a0 += fmaxf(p00.x, 0.f);
            a1 += fmaxf(p00.y, 0.f);
            a2 += fmaxf(p01.x, 0.f);
            a3 += fmaxf(p01.y, 0.f);
        }
        *(float4*)(g_pool + (size_t)d * D + col) = make_float4(a0, a1, a2, a3);
    }
}

// ---------------------------------------------------------------------------
// static = pool @ W0 ; h0 = relu(static). R10-proven scalar form.
__global__ void __launch_bounds__(256) k_gemm_w0(const float* __restrict__ W, int n)
{
    extern __shared__ float sm[];
    float* sW    = sm;            // 64 KB
    float* stage = sm + D * D;    // 32 KB

    for (int i = threadIdx.x; i < D * D; i += blockDim.x) sW[i] = W[i];
    __syncthreads();

    int warp = threadIdx.x >> 5;
    int lane = threadIdx.x & 31;
    int col  = lane * 4;
    float* st = stage + warp * (8 * D);

    for (int r0 = blockIdx.x * 64 + warp * 8; r0 < n; r0 += gridDim.x * 64) {
        int rmax = n - r0; if (rmax > 8) rmax = 8;
#pragma unroll
        for (int rr = 0; rr < 8; rr++)
            if (rr < rmax)
                *(float4*)(st + rr * D + col) =
                    *(const float4*)(g_pool + (size_t)(r0 + rr) * D + col);
        __syncwarp();

        u64 a0[8], a1[8];
#pragma unroll
        for (int rr = 0; rr < 8; rr++) { a0[rr] = 0ull; a1[rr] = 0ull; }

        for (int k = 0; k < D; k++) {
            ulonglong2 w = *(const ulonglong2*)(sW + k * D + col);
#pragma unroll
            for (int rr = 0; rr < 8; rr++) {
                u64 xx = pack2(st[rr * D + k]);
                a0[rr] = ffma2(xx, w.x, a0[rr]);
                a1[rr] = ffma2(xx, w.y, a1[rr]);
            }
        }
#pragma unroll
        for (int rr = 0; rr < 8; rr++) {
            if (rr < rmax) {
                float2 p0 = unpack2(a0[rr]), p1 = unpack2(a1[rr]);
                float4 s = make_float4(p0.x, p0.y, p1.x, p1.y);
                *(float4*)(g_static + (size_t)(r0 + rr) * D + col) = s;
                *(float4*)(g_h + (size_t)(r0 + rr) * D + col) =
                    make_float4(fmaxf(s.x, 0.f), fmaxf(s.y, 0.f),
                                fmaxf(s.z, 0.f), fmaxf(s.w, 0.f));
            }
        }
        __syncwarp();
    }
}

// ---------------------------------------------------------------------------
// wmma GEMM: [A | Yh] = h @ [W1 | W2], epilogue adds static / converts fp16.
// 512 threads = 16 warps = 4 row-groups x 4 col-groups over a 64x256 C tile.
// fp16 inputs (converted in staging), fp32 accumulate. HMMA tensor path.
__global__ void __launch_bounds__(512) k_gemmAB(
    const float* __restrict__ W1, const float* __restrict__ W2, int n)
{
    extern __shared__ char smraw[];
    __half* sW = (__half*)smraw;                         // 128 x LDW fp16 = 67584 B
    __half* sX = (__half*)(smraw + 128 * LDW * 2);       //  64 x LDX fp16 = 17408 B
    float*  sC = (float*)(smraw + 128 * LDW * 2 + 64 * LDX * 2); // 64 x LDC f32

    int tid  = threadIdx.x;
    int warp = tid >> 5;

    // Load combined weights fp32 -> fp16 (once per block)
    for (int i = tid; i < 128 * 256; i += 512) {
        int k = i >> 8;          // 0..127
        int c = i & 255;         // 0..255
        float v = (c < 128) ? W1[k * D + c] : W2[k * D + (c - 128)];
        sW[k * LDW + c] = __float2half(v);
    }
    __syncthreads();

    int rg = warp >> 2;          // row group 0..3  (rows rg*16 .. rg*16+15)
    int cg = warp & 3;           // col group 0..3  (cols cg*64 .. cg*64+63)

    wmma::fragment<wmma::matrix_a, 16, 16, 16, __half, wmma::row_major> fa;
    wmma::fragment<wmma::matrix_b, 16, 16, 16, __half, wmma::row_major> fb;
    wmma::fragment<wmma::accumulator, 16, 16, 16, float> fc[4];

    for (int r0 = blockIdx.x * 64; r0 < n; r0 += gridDim.x * 64) {
        // Stage X rows r0..r0+63 as fp16 (zero padding past n)
        for (int i = tid; i < 64 * 128; i += 512) {
            int rr = i >> 7, c = i & 127;
            float v = (r0 + rr < n) ? g_h[(size_t)(r0 + rr) * D + c] : 0.f;
            sX[rr * LDX + c] = __float2half(v);
        }
        __syncthreads();

#pragma unroll
        for (int j = 0; j < 4; j++) wmma::fill_fragment(fc[j], 0.f);

#pragma unroll
        for (int k = 0; k < 8; k++) {
            wmma::load_matrix_sync(fa, sX + (rg * 16) * LDX + k * 16, LDX);
#pragma unroll
            for (int j = 0; j < 4; j++) {
                wmma::load_matrix_sync(fb, sW + (k * 16) * LDW + cg * 64 + j * 16, LDW);
                wmma::mma_sync(fc[j], fa, fb, fc[j]);
            }
        }

#pragma unroll
        for (int j = 0; j < 4; j++)
            wmma::store_matrix_sync(sC + (rg * 16) * LDC + cg * 64 + j * 16,
                                    fc[j], LDC, wmma::mem_row_major);
        __syncthreads();

        // Epilogue: A = static + C[:,0:128]; Yh = fp16(C[:,128:256])
        for (int i = tid; i < 64 * 32; i += 512) {
            int rr = i >> 5;
            int c4 = (i & 31) * 4;
            int row = r0 + rr;
            if (row < n) {
                const float* crow = sC + rr * LDC;
                float4 s = *(const float4*)(g_static + (size_t)row * D + c4);
                float4 a = make_float4(s.x + crow[c4],     s.y + crow[c4 + 1],
                                       s.z + crow[c4 + 2], s.w + crow[c4 + 3]);
                *(float4*)(g_A + (size_t)row * D + c4) = a;
                const float* crow2 = crow + 128;
                __half2 q0 = __floats2half2_rn(crow2[c4],     crow2[c4 + 1]);
                __half2 q1 = __floats2half2_rn(crow2[c4 + 2], crow2[c4 + 3]);
                uint2 pk;
                pk.x = *(unsigned int*)&q0;
                pk.y = *(unsigned int*)&q1;
                *(uint2*)(g_Yh + (size_t)row * D + c4) = pk;
            }
        }
        __syncthreads();
    }
}

// ---------------------------------------------------------------------------
// Fused n2n spmm + merge: out[d] = relu(A[d] + sum_{src in N(d)} Yh[src])
__global__ void __launch_bounds__(256) k_spmm_merge(float* __restrict__ out, int n)
{
    int lane = threadIdx.x & 31;
    int gw   = (blockIdx.x * blockDim.x + threadIdx.x) >> 5;
    int nw   = (gridDim.x * blockDim.x) >> 5;
    float* dst = out ? out : g_h;   // device-side select (host g_h addr invalid)
    int col  = lane * 4;

    for (int d = gw; d < n; d += nw) {
        int j0 = g_off[1][d], j1 = g_off[1][d + 1];
        float4 acc0 = *(const float4*)(g_A + (size_t)d * D + col);
        float4 acc1 = make_float4(0.f, 0.f, 0.f, 0.f);
        float4 acc2 = make_float4(0.f, 0.f, 0.f, 0.f);
        float4 acc3 = make_float4(0.f, 0.f, 0.f, 0.f);

        int j = j0;
        for (; j + 4 <= j1; j += 4) {
            int s0 = g_permB[j],     s1 = g_permB[j + 1];
            int s2 = g_permB[j + 2], s3 = g_permB[j + 3];
            uint2 r0 = *(const uint2*)(g_Yh + (size_t)s0 * D + col);
            uint2 r1 = *(const uint2*)(g_Yh + (size_t)s1 * D + col);
            uint2 r2 = *(const uint2*)(g_Yh + (size_t)s2 * D + col);
            uint2 r3 = *(const uint2*)(g_Yh + (size_t)s3 * D + col);
            float2 f0a = __half22float2(*(__half2*)&r0.x), f0b = __half22float2(*(__half2*)&r0.y);
            float2 f1a = __half22float2(*(__half2*)&r1.x), f1b = __half22float2(*(__half2*)&r1.y);
            float2 f2a = __half22float2(*(__half2*)&r2.x), f2b = __half22float2(*(__half2*)&r2.y);
            float2 f3a = __half22float2(*(__half2*)&r3.x), f3b = __half22float2(*(__half2*)&r3.y);
            acc0.x += f0a.x; acc0.y += f0a.y; acc0.z += f0b.x; acc0.w += f0b.y;
            acc1.x += f1a.x; acc1.y += f1a.y; acc1.z += f1b.x; acc1.w += f1b.y;
            acc2.x += f2a.x; acc2.y += f2a.y; acc2.z += f2b.x; acc2.w += f2b.y;
            acc3.x += f3a.x; acc3.y += f3a.y; acc3.z += f3b.x; acc3.w += f3b.y;
        }
        for (; j < j1; j++) {
            int s0 = g_permB[j];
            uint2 r0 = *(const uint2*)(g_Yh + (size_t)s0 * D + col);
            float2 f0a = __half22float2(*(__half2*)&r0.x), f0b = __half22float2(*(__half2*)&r0.y);
            acc0.x += f0a.x; acc0.y += f0a.y; acc0.z += f0b.x; acc0.w += f0b.y;
        }
        float4 o;
        o.x = fmaxf(acc0.x + acc1.x + acc2.x + acc3.x, 0.f);
        o.y = fmaxf(acc0.y + acc1.y + acc2.y + acc3.y, 0.f);
        o.z = fmaxf(acc0.z + acc1.z + acc2.z + acc3.z, 0.f);
        o.w = fmaxf(acc0.w + acc1.w + acc2.w + acc3.w, 0.f);
        *(float4*)(dst + (size_t)d * D + col) = o;
    }
}

// ---------------------------------------------------------------------------
extern "C" void kernel_launch(void* const* d_in, const int* in_sizes, int n_in,
                              void* d_out, int out_size)
{
    const float* edge_feat = (const float*)d_in[0];
    const float* W_e2l     = (const float*)d_in[1];
    const float* W0        = (const float*)d_in[2];
    const float* W1s[3] = { (const float*)d_in[3], (const float*)d_in[5], (const float*)d_in[7] };
    const float* W2s[3] = { (const float*)d_in[4], (const float*)d_in[6], (const float*)d_in[8] };
    const int* e2n_dst  = (const int*)d_in[9];
    const int* edge_src = (const int*)d_in[10];
    const int* edge_dst = (const int*)d_in[11];

    int E = in_sizes[9];
    int n = out_size / D;
    int nchunk = (n + 255) / 256;

    const int smem_w0 = (D * D + 8 * 8 * D) * (int)sizeof(float);            //  96 KB
    const int smem_ab = 128 * LDW * 2 + 64 * LDX * 2 + 64 * LDC * 4;         // ~149 KB
    cudaFuncSetAttribute(k_gemm_w0, cudaFuncAttributeMaxDynamicSharedMemorySize, smem_w0);
    cudaFuncSetAttribute(k_gemmAB,  cudaFuncAttributeMaxDynamicSharedMemorySize, smem_ab);

    int node_blocks = (n + 7) / 8;     // warp per node
    int e4_blocks   = (E / 4 + 255) / 256;

    // --- CSR build ---
    k_zero_cnt<<<196, 256>>>(n);
    k_hist<<<e4_blocks, 256>>>(e2n_dst, edge_dst, E);
    dim3 sg(nchunk, 2);
    k_scan1<<<sg, 256>>>(n);
    k_scan2<<<1, 256>>>(n, nchunk);
    k_scan3<<<sg, 256>>>(n);
    k_fill<<<e4_blocks, 256>>>(e2n_dst, edge_dst, edge_src, E);

    // --- node pipeline ---
    k_edge_pool<<<node_blocks, 256>>>(edge_feat, W_e2l, n);
    k_gemm_w0<<<296, 256, smem_w0>>>(W0, n);

    for (int it = 0; it < 3; it++) {
        k_gemmAB<<<148, 512, smem_ab>>>(W1s[it], W2s[it], n);
        k_spmm_merge<<<node_blocks, 256>>>(it == 2 ? (float*)d_out : nullptr, n);
    }
}

// round 14
// speedup vs baseline: 1.4420x; 1.0715x over previous
#include <cuda_runtime.h>
#include <cuda_fp16.h>
#include <mma.h>

using namespace nvcuda;

#define D      128
#define EF     16
#define NMAX   50000
#define EMAX   1600000
#define NCHUNK_MAX 256   // ceil(NMAX/256) = 196 <= 256

typedef unsigned long long u64;

// wmma staging leading dims (padded to dodge bank conflicts)
#define LDX 136      // fp16 X stage:    64 x 136
#define LDW 264      // fp16 W1|W2:     128 x 264
#define LDC 264      // fp32 C stage:    64 x 264
#define LDW0 136     // fp16 W0:        128 x 136
#define LDC0 136     // fp32 C stage:    64 x 136

// ---------------- scratch (device globals; zero-init, no allocation) -------
__device__ float  g_pool[NMAX * D];    // e2n pooled edge messages
__device__ float  g_static[NMAX * D];  // e2n_pool @ W0 (pre-relu)
__device__ float  g_A[NMAX * D];       // static + h @ W1
__device__ __half g_Yh[NMAX * D];      // h @ W2, fp16
__device__ float  g_h[NMAX * D];       // hidden state

__device__ int g_cnt[2][NMAX];
__device__ int g_off[2][NMAX + 1];
__device__ int g_cur[2][NMAX];
__device__ int g_csum[2][NCHUNK_MAX];
__device__ int g_coff[2][NCHUNK_MAX];
__device__ int g_permA[EMAX];          // edge ids grouped by e2n_dst
__device__ int g_permB[EMAX];          // edge_src values grouped by edge_dst

// ---------------- f32x2 packed math helpers --------------------------------
__device__ __forceinline__ u64 pack2(float x) {
    unsigned int u = __float_as_uint(x);
    u64 r;
    asm("mov.b64 %0, {%1, %2};" : "=l"(r) : "r"(u), "r"(u));
    return r;
}
__device__ __forceinline__ u64 ffma2(u64 a, u64 b, u64 c) {
    u64 d;
    asm("fma.rn.f32x2 %0, %1, %2, %3;" : "=l"(d) : "l"(a), "l"(b), "l"(c));
    return d;
}
__device__ __forceinline__ float2 unpack2(u64 v) {
    unsigned int lo, hi;
    asm("mov.b64 {%0, %1}, %2;" : "=r"(lo), "=r"(hi) : "l"(v));
    return make_float2(__uint_as_float(lo), __uint_as_float(hi));
}

// ---------------- CSR builders ---------------------------------------------
__global__ void k_zero_cnt(int n) {
    int i = blockIdx.x * blockDim.x + threadIdx.x;
    int s = gridDim.x * blockDim.x;
    for (; i < n; i += s) { g_cnt[0][i] = 0; g_cnt[1][i] = 0; }
}

__global__ void k_hist(const int* __restrict__ e2n, const int* __restrict__ ndst, int E) {
    int E4 = E >> 2;
    int i = blockIdx.x * blockDim.x + threadIdx.x;
    int s = gridDim.x * blockDim.x;
    for (; i < E4; i += s) {
        int4 a = ((const int4*)e2n)[i];
        int4 b = ((const int4*)ndst)[i];
        atomicAdd(&g_cnt[0][a.x], 1); atomicAdd(&g_cnt[0][a.y], 1);
        atomicAdd(&g_cnt[0][a.z], 1); atomicAdd(&g_cnt[0][a.w], 1);
        atomicAdd(&g_cnt[1][b.x], 1); atomicAdd(&g_cnt[1][b.y], 1);
        atomicAdd(&g_cnt[1][b.z], 1); atomicAdd(&g_cnt[1][b.w], 1);
    }
    int t = E4 * 4 + (blockIdx.x * blockDim.x + threadIdx.x);
    if (t < E) {
        atomicAdd(&g_cnt[0][e2n[t]], 1);
        atomicAdd(&g_cnt[1][ndst[t]], 1);
    }
}

__global__ void k_scan1(int n) {
    __shared__ int sh[256];
    int a = blockIdx.y;
    int i = blockIdx.x * 256 + threadIdx.x;
    sh[threadIdx.x] = (i < n) ? g_cnt[a][i] : 0;
    __syncthreads();
    for (int o = 128; o > 0; o >>= 1) {
        if (threadIdx.x < o) sh[threadIdx.x] += sh[threadIdx.x + o];
        __syncthreads();
    }
    if (threadIdx.x == 0) g_csum[a][blockIdx.x] = sh[0];
}

__global__ void k_scan2(int n, int nchunk) {
    __shared__ int sh[256];
    for (int a = 0; a < 2; a++) {
        int v = (threadIdx.x < nchunk) ? g_csum[a][threadIdx.x] : 0;
        sh[threadIdx.x] = v;
        __syncthreads();
        for (int o = 1; o < 256; o <<= 1) {
            int t = (threadIdx.x >= o) ? sh[threadIdx.x - o] : 0;
            __syncthreads();
            sh[threadIdx.x] += t;
            __syncthreads();
        }
        if (threadIdx.x < nchunk) g_coff[a][threadIdx.x] = sh[threadIdx.x] - v;
        if (threadIdx.x == 255)   g_off[a][n] = sh[255];
        __syncthreads();
    }
}

__global__ void k_scan3(int n) {
    __shared__ int sh[256];
    int a = blockIdx.y;
    int i = blockIdx.x * 256 + threadIdx.x;
    int v = (i < n) ? g_cnt[a][i] : 0;
    sh[threadIdx.x] = v;
    __syncthreads();
    for (int o = 1; o < 256; o <<= 1) {
        int t = (threadIdx.x >= o) ? sh[threadIdx.x - o] : 0;
        __syncthreads();
        sh[threadIdx.x] += t;
        __syncthreads();
    }
    if (i < n) {
        int excl = g_coff[a][blockIdx.x] + sh[threadIdx.x] - v;
        g_off[a][i] = excl;
        g_cur[a][i] = excl;
    }
}

__global__ void k_fill(const int* __restrict__ e2n, const int* __restrict__ ndst,
                       const int* __restrict__ nsrc, int E) {
    int E4 = E >> 2;
    int i = blockIdx.x * blockDim.x + threadIdx.x;
    int s = gridDim.x * blockDim.x;
    for (; i < E4; i += s) {
        int4 a = ((const int4*)e2n)[i];
        int4 b = ((const int4*)ndst)[i];
        int4 c = ((const int4*)nsrc)[i];
        int base = i * 4;
        int pa0 = atomicAdd(&g_cur[0][a.x], 1);
        int pa1 = atomicAdd(&g_cur[0][a.y], 1);
        int pa2 = atomicAdd(&g_cur[0][a.z], 1);
        int pa3 = atomicAdd(&g_cur[0][a.w], 1);
        int pb0 = atomicAdd(&g_cur[1][b.x], 1);
        int pb1 = atomicAdd(&g_cur[1][b.y], 1);
        int pb2 = atomicAdd(&g_cur[1][b.z], 1);
        int pb3 = atomicAdd(&g_cur[1][b.w], 1);
        g_permA[pa0] = base;     g_permA[pa1] = base + 1;
        g_permA[pa2] = base + 2; g_permA[pa3] = base + 3;
        g_permB[pb0] = c.x; g_permB[pb1] = c.y;
        g_permB[pb2] = c.z; g_permB[pb3] = c.w;
    }
    int t = E4 * 4 + (blockIdx.x * blockDim.x + threadIdx.x);
    if (t < E) {
        int pa = atomicAdd(&g_cur[0][e2n[t]], 1);
        g_permA[pa] = t;
        int pb = atomicAdd(&g_cur[1][ndst[t]], 1);
        g_permB[pb] = nsrc[t];
    }
}

// ---------------------------------------------------------------------------
// Per-node e2n pool. Weights in registers; edge loop unrolled x2. (R10-proven)
__global__ void __launch_bounds__(256) k_edge_pool(
    const float* __restrict__ ef, const float* __restrict__ We, int n)
{
    int lane = threadIdx.x & 31;
    int col  = lane * 4;

    ulonglong2 w[EF];
#pragma unroll
    for (int k = 0; k < EF; k++)
        w[k] = *(const ulonglong2*)(We + k * D + col);

    int gw = (blockIdx.x * blockDim.x + threadIdx.x) >> 5;
    int nw = (gridDim.x * blockDim.x) >> 5;

    for (int d = gw; d < n; d += nw) {
        int j0 = g_off[0][d], j1 = g_off[0][d + 1];
        float a0 = 0.f, a1 = 0.f, a2 = 0.f, a3 = 0.f;

        int j = j0;
        for (; j + 2 <= j1; j += 2) {
            int e0 = g_permA[j], e1 = g_permA[j + 1];
            float f0 = (lane < EF) ? ef[(size_t)e0 * EF + lane] : 0.f;
            float f1 = (lane < EF) ? ef[(size_t)e1 * EF + lane] : 0.f;
            u64 t00 = 0ull, t01 = 0ull, t10 = 0ull, t11 = 0ull;
#pragma unroll
            for (int k = 0; k < EF; k++) {
                u64 x0 = pack2(__shfl_sync(0xffffffffu, f0, k));
                u64 x1 = pack2(__shfl_sync(0xffffffffu, f1, k));
                t00 = ffma2(x0, w[k].x, t00);
                t01 = ffma2(x0, w[k].y, t01);
                t10 = ffma2(x1, w[k].x, t10);
                t11 = ffma2(x1, w[k].y, t11);
            }
            float2 p00 = unpack2(t00), p01 = unpack2(t01);
            float2 p10 = unpack2(t10), p11 = unpack2(t11);
            a0 += fmaxf(p00.x, 0.f) + fmaxf(p10.x, 0.f);
            a1 += fmaxf(p00.y, 0.f) + fmaxf(p10.y, 0.f);
            a2 += fmaxf(p01.x, 0.f) + fmaxf(p11.x, 0.f);
            a3 += fmaxf(p01.y, 0.f) + fmaxf(p11.y, 0.f);
        }
        if (j < j1) {
            int e0 = g_permA[j];
            float f0 = (lane < EF) ? ef[(size_t)e0 * EF + lane] : 0.f;
            u64 t00 = 0ull, t01 = 0ull;
#pragma unroll
            for (int k = 0; k < EF; k++) {
                u64 x0 = pack2(__shfl_sync(0xffffffffu, f0, k));
                t00 = ffma2(x0, w[k].x, t00);
                t01 = ffma2(x0, w[k].y, t01);
            }
            float2 p00 = unpack2(t00), p01 = unpack2(t01);
            a0 += fmaxf(p00.x, 0.f);
            a1 += fmaxf(p00.y, 0.f);
            a2 += fmaxf(p01.x, 0.f);
            a3 += fmaxf(p01.y, 0.f);
        }
        *(float4*)(g_pool + (size_t)d * D + col) = make_float4(a0, a1, a2, a3);
    }
}

// ---------------------------------------------------------------------------
// wmma W0 GEMM: static = pool @ W0 ; h = relu(static).
// 256 threads = 8 warps = 4 row-groups x 2 col-groups over a 64x128 C tile.
__global__ void __launch_bounds__(256) k_gemm_w0(const float* __restrict__ W, int n)
{
    extern __shared__ char smraw[];
    __half* sW = (__half*)smraw;                           // 128 x LDW0 fp16
    __half* sX = (__half*)(smraw + 128 * LDW0 * 2);        //  64 x LDX  fp16
    float*  sC = (float*)(smraw + 128 * LDW0 * 2 + 64 * LDX * 2); // 64 x LDC0 f32

    int tid  = threadIdx.x;
    int warp = tid >> 5;

    for (int i = tid; i < 128 * 128; i += 256) {
        int k = i >> 7, c = i & 127;
        sW[k * LDW0 + c] = __float2half(W[k * D + c]);
    }
    __syncthreads();

    int rg = warp >> 1;          // 0..3
    int cg = warp & 1;           // 0..1 (64 cols each)

    wmma::fragment<wmma::matrix_a, 16, 16, 16, __half, wmma::row_major> fa;
    wmma::fragment<wmma::matrix_b, 16, 16, 16, __half, wmma::row_major> fb;
    wmma::fragment<wmma::accumulator, 16, 16, 16, float> fc[4];

    for (int r0 = blockIdx.x * 64; r0 < n; r0 += gridDim.x * 64) {
        for (int i = tid; i < 64 * 128; i += 256) {
            int rr = i >> 7, c = i & 127;
            float v = (r0 + rr < n) ? g_pool[(size_t)(r0 + rr) * D + c] : 0.f;
            sX[rr * LDX + c] = __float2half(v);
        }
        __syncthreads();

#pragma unroll
        for (int j = 0; j < 4; j++) wmma::fill_fragment(fc[j], 0.f);

#pragma unroll
        for (int k = 0; k < 8; k++) {
            wmma::load_matrix_sync(fa, sX + (rg * 16) * LDX + k * 16, LDX);
#pragma unroll
            for (int j = 0; j < 4; j++) {
                wmma::load_matrix_sync(fb, sW + (k * 16) * LDW0 + cg * 64 + j * 16, LDW0);
                wmma::mma_sync(fc[j], fa, fb, fc[j]);
            }
        }

#pragma unroll
        for (int j = 0; j < 4; j++)
            wmma::store_matrix_sync(sC + (rg * 16) * LDC0 + cg * 64 + j * 16,
                                    fc[j], LDC0, wmma::mem_row_major);
        __syncthreads();

        for (int i = tid; i < 64 * 32; i += 256) {
            int rr = i >> 5;
            int c4 = (i & 31) * 4;
            int row = r0 + rr;
            if (row < n) {
                const float* crow = sC + rr * LDC0;
                float4 s = make_float4(crow[c4], crow[c4 + 1], crow[c4 + 2], crow[c4 + 3]);
                *(float4*)(g_static + (size_t)row * D + c4) = s;
                *(float4*)(g_h + (size_t)row * D + c4) =
                    make_float4(fmaxf(s.x, 0.f), fmaxf(s.y, 0.f),
                                fmaxf(s.z, 0.f), fmaxf(s.w, 0.f));
            }
        }
        __syncthreads();
    }
}

// ---------------------------------------------------------------------------
// wmma GEMM: [A | Yh] = h @ [W1 | W2] (R13-proven).
__global__ void __launch_bounds__(512) k_gemmAB(
    const float* __restrict__ W1, const float* __restrict__ W2, int n)
{
    extern __shared__ char smraw[];
    __half* sW = (__half*)smraw;                         // 128 x LDW fp16
    __half* sX = (__half*)(smraw + 128 * LDW * 2);       //  64 x LDX fp16
    float*  sC = (float*)(smraw + 128 * LDW * 2 + 64 * LDX * 2); // 64 x LDC f32

    int tid  = threadIdx.x;
    int warp = tid >> 5;

    for (int i = tid; i < 128 * 256; i += 512) {
        int k = i >> 8;
        int c = i & 255;
        float v = (c < 128) ? W1[k * D + c] : W2[k * D + (c - 128)];
        sW[k * LDW + c] = __float2half(v);
    }
    __syncthreads();

    int rg = warp >> 2;
    int cg = warp & 3;

    wmma::fragment<wmma::matrix_a, 16, 16, 16, __half, wmma::row_major> fa;
    wmma::fragment<wmma::matrix_b, 16, 16, 16, __half, wmma::row_major> fb;
    wmma::fragment<wmma::accumulator, 16, 16, 16, float> fc[4];

    for (int r0 = blockIdx.x * 64; r0 < n; r0 += gridDim.x * 64) {
        for (int i = tid; i < 64 * 128; i += 512) {
            int rr = i >> 7, c = i & 127;
            float v = (r0 + rr < n) ? g_h[(size_t)(r0 + rr) * D + c] : 0.f;
            sX[rr * LDX + c] = __float2half(v);
        }
        __syncthreads();

#pragma unroll
        for (int j = 0; j < 4; j++) wmma::fill_fragment(fc[j], 0.f);

#pragma unroll
        for (int k = 0; k < 8; k++) {
            wmma::load_matrix_sync(fa, sX + (rg * 16) * LDX + k * 16, LDX);
#pragma unroll
            for (int j = 0; j < 4; j++) {
                wmma::load_matrix_sync(fb, sW + (k * 16) * LDW + cg * 64 + j * 16, LDW);
                wmma::mma_sync(fc[j], fa, fb, fc[j]);
            }
        }

#pragma unroll
        for (int j = 0; j < 4; j++)
            wmma::store_matrix_sync(sC + (rg * 16) * LDC + cg * 64 + j * 16,
                                    fc[j], LDC, wmma::mem_row_major);
        __syncthreads();

        for (int i = tid; i < 64 * 32; i += 512) {
            int rr = i >> 5;
            int c4 = (i & 31) * 4;
            int row = r0 + rr;
            if (row < n) {
                const float* crow = sC + rr * LDC;
                float4 s = *(const float4*)(g_static + (size_t)row * D + c4);
                float4 a = make_float4(s.x + crow[c4],     s.y + crow[c4 + 1],
                                       s.z + crow[c4 + 2], s.w + crow[c4 + 3]);
                *(float4*)(g_A + (size_t)row * D + c4) = a;
                const float* crow2 = crow + 128;
                __half2 q0 = __floats2half2_rn(crow2[c4],     crow2[c4 + 1]);
                __half2 q1 = __floats2half2_rn(crow2[c4 + 2], crow2[c4 + 3]);
                uint2 pk;
                pk.x = *(unsigned int*)&q0;
                pk.y = *(unsigned int*)&q1;
                *(uint2*)(g_Yh + (size_t)row * D + c4) = pk;
            }
        }
        __syncthreads();
    }
}

// ---------------------------------------------------------------------------
// Fused n2n spmm + merge, unroll x8 for deeper gather MLP.
__global__ void __launch_bounds__(256) k_spmm_merge(float* __restrict__ out, int n)
{
    int lane = threadIdx.x & 31;
    int gw   = (blockIdx.x * blockDim.x + threadIdx.x) >> 5;
    int nw   = (gridDim.x * blockDim.x) >> 5;
    float* dst = out ? out : g_h;   // device-side select (host g_h addr invalid)
    int col  = lane * 4;

    for (int d = gw; d < n; d += nw) {
        int j0 = g_off[1][d], j1 = g_off[1][d + 1];
        float4 acc0 = *(const float4*)(g_A + (size_t)d * D + col);
        float4 acc1 = make_float4(0.f, 0.f, 0.f, 0.f);
        float4 acc2 = make_float4(0.f, 0.f, 0.f, 0.f);
        float4 acc3 = make_float4(0.f, 0.f, 0.f, 0.f);

        int j = j0;
        for (; j + 8 <= j1; j += 8) {
            int s0 = __ldg(g_permB + j),     s1 = __ldg(g_permB + j + 1);
            int s2 = __ldg(g_permB + j + 2), s3 = __ldg(g_permB + j + 3);
            int s4 = __ldg(g_permB + j + 4), s5 = __ldg(g_permB + j + 5);
            int s6 = __ldg(g_permB + j + 6), s7 = __ldg(g_permB + j + 7);
            uint2 r0 = *(const uint2*)(g_Yh + (size_t)s0 * D + col);
            uint2 r1 = *(const uint2*)(g_Yh + (size_t)s1 * D + col);
            uint2 r2 = *(const uint2*)(g_Yh + (size_t)s2 * D + col);
            uint2 r3 = *(const uint2*)(g_Yh + (size_t)s3 * D + col);
            uint2 r4 = *(const uint2*)(g_Yh + (size_t)s4 * D + col);
            uint2 r5 = *(const uint2*)(g_Yh + (size_t)s5 * D + col);
            uint2 r6 = *(const uint2*)(g_Yh + (size_t)s6 * D + col);
            uint2 r7 = *(const uint2*)(g_Yh + (size_t)s7 * D + col);
            float2 fa, fb;
#define ACC(P, R) \
            fa = __half22float2(*(__half2*)&R.x); fb = __half22float2(*(__half2*)&R.y); \
            P.x += fa.x; P.y += fa.y; P.z += fb.x; P.w += fb.y;
            ACC(acc0, r0) ACC(acc1, r1) ACC(acc2, r2) ACC(acc3, r3)
            ACC(acc0, r4) ACC(acc1, r5) ACC(acc2, r6) ACC(acc3, r7)
        }
        for (; j + 4 <= j1; j += 4) {
            int s0 = __ldg(g_permB + j),     s1 = __ldg(g_permB + j + 1);
            int s2 = __ldg(g_permB + j + 2), s3 = __ldg(g_permB + j + 3);
            uint2 r0 = *(const uint2*)(g_Yh + (size_t)s0 * D + col);
            uint2 r1 = *(const uint2*)(g_Yh + (size_t)s1 * D + col);
            uint2 r2 = *(const uint2*)(g_Yh + (size_t)s2 * D + col);
            uint2 r3 = *(const uint2*)(g_Yh + (size_t)s3 * D + col);
            float2 fa, fb;
            ACC(acc0, r0) ACC(acc1, r1) ACC(acc2, r2) ACC(acc3, r3)
        }
        for (; j < j1; j++) {
            int s0 = __ldg(g_permB + j);
            uint2 r0 = *(const uint2*)(g_Yh + (size_t)s0 * D + col);
            float2 fa, fb;
            ACC(acc0, r0)
        }
#undef ACC
        float4 o;
        o.x = fmaxf(acc0.x + acc1.x + acc2.x + acc3.x, 0.f);
        o.y = fmaxf(acc0.y + acc1.y + acc2.y + acc3.y, 0.f);
        o.z = fmaxf(acc0.z + acc1.z + acc2.z + acc3.z, 0.f);
        o.w = fmaxf(acc0.w + acc1.w + acc2.w + acc3.w, 0.f);
        *(float4*)(dst + (size_t)d * D + col) = o;
    }
}

// ---------------------------------------------------------------------------
extern "C" void kernel_launch(void* const* d_in, const int* in_sizes, int n_in,
                              void* d_out, int out_size)
{
    const float* edge_feat = (const float*)d_in[0];
    const float* W_e2l     = (const float*)d_in[1];
    const float* W0        = (const float*)d_in[2];
    const float* W1s[3] = { (const float*)d_in[3], (const float*)d_in[5], (const float*)d_in[7] };
    const float* W2s[3] = { (const float*)d_in[4], (const float*)d_in[6], (const float*)d_in[8] };
    const int* e2n_dst  = (const int*)d_in[9];
    const int* edge_src = (const int*)d_in[10];
    const int* edge_dst = (const int*)d_in[11];

    int E = in_sizes[9];
    int n = out_size / D;
    int nchunk = (n + 255) / 256;

    const int smem_w0 = 128 * LDW0 * 2 + 64 * LDX * 2 + 64 * LDC0 * 4;       // ~86 KB
    const int smem_ab = 128 * LDW * 2 + 64 * LDX * 2 + 64 * LDC * 4;         // ~149 KB
    cudaFuncSetAttribute(k_gemm_w0, cudaFuncAttributeMaxDynamicSharedMemorySize, smem_w0);
    cudaFuncSetAttribute(k_gemmAB,  cudaFuncAttributeMaxDynamicSharedMemorySize, smem_ab);

    int node_blocks = (n + 7) / 8;     // warp per node
    int e4_blocks   = (E / 4 + 255) / 256;

    // --- CSR build ---
    k_zero_cnt<<<196, 256>>>(n);
    k_hist<<<e4_blocks, 256>>>(e2n_dst, edge_dst, E);
    dim3 sg(nchunk, 2);
    k_scan1<<<sg, 256>>>(n);
    k_scan2<<<1, 256>>>(n, nchunk);
    k_scan3<<<sg, 256>>>(n);
    k_fill<<<e4_blocks, 256>>>(e2n_dst, edge_dst, edge_src, E);

    // --- node pipeline ---
    k_edge_pool<<<node_blocks, 256>>>(edge_feat, W_e2l, n);
    k_gemm_w0<<<296, 256, smem_w0>>>(W0, n);

    for (int it = 0; it < 3; it++) {
        k_gemmAB<<<148, 512, smem_ab>>>(W1s[it], W2s[it], n);
        k_spmm_merge<<<node_blocks, 256>>>(it == 2 ? (float*)d_out : nullptr, n);
    }
}

// round 16
// speedup vs baseline: 1.4832x; 1.0286x over previous
#include <cuda_runtime.h>
#include <cuda_fp16.h>
#include <mma.h>

using namespace nvcuda;

#define D      128
#define EF     16
#define NMAX   50000
#define EMAX   1600000
#define NCHUNK_MAX 256   // ceil(NMAX/256) = 196 <= 256

typedef unsigned long long u64;

// wmma staging leading dims (padded to dodge bank conflicts; all ldm values
// are multiples of 16 bytes as required by load/store_matrix_sync)
#define LDX 136      // fp16 X stage:    64 x 136
#define LDW 264      // fp16 W1|W2:     128 x 264
#define LDC 264      // fp32 C stage:    64 x 264
#define LDW0 136     // fp16 W0:        128 x 136
#define LDC0 136     // fp32 C stage:    64 x 136
#define LDE 24       // fp16 edge A tile: 16 x 24 (48B rows)
#define LDR 20       // fp32 reduce tile: 16 x 20 (80B rows, mult of 16B)

// ---------------- scratch (device globals; zero-init, no allocation) -------
__device__ float  g_pool[NMAX * D];    // e2n pooled edge messages
__device__ float  g_static[NMAX * D];  // e2n_pool @ W0 (pre-relu)
__device__ float  g_A[NMAX * D];       // static + h @ W1
__device__ __half g_Yh[NMAX * D];      // h @ W2, fp16
__device__ float  g_h[NMAX * D];       // hidden state

__device__ int g_cnt[2][NMAX];
__device__ int g_off[2][NMAX + 1];
__device__ int g_cur[2][NMAX];
__device__ int g_csum[2][NCHUNK_MAX];
__device__ int g_coff[2][NCHUNK_MAX];
__device__ int g_permA[EMAX];          // edge ids grouped by e2n_dst
__device__ int g_permB[EMAX];          // edge_src values grouped by edge_dst

// ---------------- CSR builders ---------------------------------------------
__global__ void k_zero_cnt(int n) {
    int i = blockIdx.x * blockDim.x + threadIdx.x;
    int s = gridDim.x * blockDim.x;
    for (; i < n; i += s) { g_cnt[0][i] = 0; g_cnt[1][i] = 0; }
}

__global__ void k_hist(const int* __restrict__ e2n, const int* __restrict__ ndst, int E) {
    int E4 = E >> 2;
    int i = blockIdx.x * blockDim.x + threadIdx.x;
    int s = gridDim.x * blockDim.x;
    for (; i < E4; i += s) {
        int4 a = ((const int4*)e2n)[i];
        int4 b = ((const int4*)ndst)[i];
        atomicAdd(&g_cnt[0][a.x], 1); atomicAdd(&g_cnt[0][a.y], 1);
        atomicAdd(&g_cnt[0][a.z], 1); atomicAdd(&g_cnt[0][a.w], 1);
        atomicAdd(&g_cnt[1][b.x], 1); atomicAdd(&g_cnt[1][b.y], 1);
        atomicAdd(&g_cnt[1][b.z], 1); atomicAdd(&g_cnt[1][b.w], 1);
    }
    int t = E4 * 4 + (blockIdx.x * blockDim.x + threadIdx.x);
    if (t < E) {
        atomicAdd(&g_cnt[0][e2n[t]], 1);
        atomicAdd(&g_cnt[1][ndst[t]], 1);
    }
}

__global__ void k_scan1(int n) {
    __shared__ int sh[256];
    int a = blockIdx.y;
    int i = blockIdx.x * 256 + threadIdx.x;
    sh[threadIdx.x] = (i < n) ? g_cnt[a][i] : 0;
    __syncthreads();
    for (int o = 128; o > 0; o >>= 1) {
        if (threadIdx.x < o) sh[threadIdx.x] += sh[threadIdx.x + o];
        __syncthreads();
    }
    if (threadIdx.x == 0) g_csum[a][blockIdx.x] = sh[0];
}

__global__ void k_scan2(int n, int nchunk) {
    __shared__ int sh[256];
    for (int a = 0; a < 2; a++) {
        int v = (threadIdx.x < nchunk) ? g_csum[a][threadIdx.x] : 0;
        sh[threadIdx.x] = v;
        __syncthreads();
        for (int o = 1; o < 256; o <<= 1) {
            int t = (threadIdx.x >= o) ? sh[threadIdx.x - o] : 0;
            __syncthreads();
            sh[threadIdx.x] += t;
            __syncthreads();
        }
        if (threadIdx.x < nchunk) g_coff[a][threadIdx.x] = sh[threadIdx.x] - v;
        if (threadIdx.x == 255)   g_off[a][n] = sh[255];
        __syncthreads();
    }
}

__global__ void k_scan3(int n) {
    __shared__ int sh[256];
    int a = blockIdx.y;
    int i = blockIdx.x * 256 + threadIdx.x;
    int v = (i < n) ? g_cnt[a][i] : 0;
    sh[threadIdx.x] = v;
    __syncthreads();
    for (int o = 1; o < 256; o <<= 1) {
        int t = (threadIdx.x >= o) ? sh[threadIdx.x - o] : 0;
        __syncthreads();
        sh[threadIdx.x] += t;
        __syncthreads();
    }
    if (i < n) {
        int excl = g_coff[a][blockIdx.x] + sh[threadIdx.x] - v;
        g_off[a][i] = excl;
        g_cur[a][i] = excl;
    }
}

__global__ void k_fill(const int* __restrict__ e2n, const int* __restrict__ ndst,
                       const int* __restrict__ nsrc, int E) {
    int E4 = E >> 2;
    int i = blockIdx.x * blockDim.x + threadIdx.x;
    int s = gridDim.x * blockDim.x;
    for (; i < E4; i += s) {
        int4 a = ((const int4*)e2n)[i];
        int4 b = ((const int4*)ndst)[i];
        int4 c = ((const int4*)nsrc)[i];
        int base = i * 4;
        int pa0 = atomicAdd(&g_cur[0][a.x], 1);
        int pa1 = atomicAdd(&g_cur[0][a.y], 1);
        int pa2 = atomicAdd(&g_cur[0][a.z], 1);
        int pa3 = atomicAdd(&g_cur[0][a.w], 1);
        int pb0 = atomicAdd(&g_cur[1][b.x], 1);
        int pb1 = atomicAdd(&g_cur[1][b.y], 1);
        int pb2 = atomicAdd(&g_cur[1][b.z], 1);
        int pb3 = atomicAdd(&g_cur[1][b.w], 1);
        g_permA[pa0] = base;     g_permA[pa1] = base + 1;
        g_permA[pa2] = base + 2; g_permA[pa3] = base + 3;
        g_permB[pb0] = c.x; g_permB[pb1] = c.y;
        g_permB[pb2] = c.z; g_permB[pb3] = c.w;
    }
    int t = E4 * 4 + (blockIdx.x * blockDim.x + threadIdx.x);
    if (t < E) {
        int pa = atomicAdd(&g_cur[0][e2n[t]], 1);
        g_permA[pa] = t;
        int pb = atomicAdd(&g_cur[1][ndst[t]], 1);
        g_permB[pb] = nsrc[t];
    }
}

// ---------------------------------------------------------------------------
// wmma e2n pool: pool[d] = sum_{e in N(d)} relu(ef[e] @ We).
// Warp per node. 16-edge chunks -> m16n16k16 HMMA, relu fused in the
// accumulator fragment, chunk sums folded fragment-wise; final 16-row
// column sum via a properly-aligned (LDR=20) staging tile.
__global__ void __launch_bounds__(256) k_edge_pool(
    const float* __restrict__ ef, const float* __restrict__ We, int n)
{
    __shared__ __half sWe[EF * LDW0];          // 16 x 136 fp16
    __shared__ __half sA[8][16 * LDE];         // per-warp edge tile
    __shared__ float  sR[8][16 * LDR];         // per-warp reduce tile

    int tid  = threadIdx.x;
    int warp = tid >> 5;
    int lane = tid & 31;

    for (int i = tid; i < EF * D; i += 256) {
        int k = i >> 7, c = i & 127;
        sWe[k * LDW0 + c] = __float2half(We[i]);
    }
    __syncthreads();

    wmma::fragment<wmma::matrix_a, 16, 16, 16, __half, wmma::row_major> fa;
    wmma::fragment<wmma::matrix_b, 16, 16, 16, __half, wmma::row_major> fB[8];
#pragma unroll
    for (int j = 0; j < 8; j++)
        wmma::load_matrix_sync(fB[j], sWe + j * 16, LDW0);

    wmma::fragment<wmma::accumulator, 16, 16, 16, float> pool[8], work;

    int gw = blockIdx.x * 8 + warp;
    int nw = gridDim.x * 8;
    int slot = lane >> 1;        // edge slot 0..15 this lane stages
    int half_ = lane & 1;        // which 8 features

    for (int d = gw; d < n; d += nw) {
        int j0 = g_off[0][d], j1 = g_off[0][d + 1];
#pragma unroll
        for (int j = 0; j < 8; j++) wmma::fill_fragment(pool[j], 0.f);

        for (int base = j0; base < j1; base += 16) {
            uint4 pk = make_uint4(0u, 0u, 0u, 0u);
            int er = base + slot;
            if (er < j1) {
                int e = g_permA[er];
                const float4* p = (const float4*)(ef + (size_t)e * EF + half_ * 8);
                float4 v0 = p[0], v1 = p[1];
                __half2 h0 = __floats2half2_rn(v0.x, v0.y);
                __half2 h1 = __floats2half2_rn(v0.z, v0.w);
                __half2 h2 = __floats2half2_rn(v1.x, v1.y);
                __half2 h3 = __floats2half2_rn(v1.z, v1.w);
                pk.x = *(unsigned int*)&h0;
                pk.y = *(unsigned int*)&h1;
                pk.z = *(unsigned int*)&h2;
                pk.w = *(unsigned int*)&h3;
            }
            *(uint4*)(&sA[warp][slot * LDE + half_ * 8]) = pk;
            __syncwarp();

            wmma::load_matrix_sync(fa, sA[warp], LDE);
#pragma unroll
            for (int j = 0; j < 8; j++) {
                wmma::fill_fragment(work, 0.f);
                wmma::mma_sync(work, fa, fB[j], work);
#pragma unroll
                for (int t = 0; t < work.num_elements; t++)
                    pool[j].x[t] += fmaxf(work.x[t], 0.f);
            }
            __syncwarp();
        }

        // reduce: each pool frag is [16 rows x 16 cols]; column-sum rows.
#pragma unroll
        for (int j = 0; j < 8; j++) {
            wmma::store_matrix_sync(sR[warp], pool[j], LDR, wmma::mem_row_major);
            __syncwarp();
            if (lane < 16) {
                float s = 0.f;
#pragma unroll
                for (int r = 0; r < 16; r++) s += sR[warp][r * LDR + lane];
                g_pool[(size_t)d * D + j * 16 + lane] = s;
            }
            __syncwarp();
        }
    }
}

// ---------------------------------------------------------------------------
// wmma W0 GEMM: static = pool @ W0 ; h = relu(static). (R14-proven)
__global__ void __launch_bounds__(256) k_gemm_w0(const float* __restrict__ W, int n)
{
    extern __shared__ char smraw[];
    __half* sW = (__half*)smraw;                           // 128 x LDW0 fp16
    __half* sX = (__half*)(smraw + 128 * LDW0 * 2);        //  64 x LDX  fp16
    float*  sC = (float*)(smraw + 128 * LDW0 * 2 + 64 * LDX * 2); // 64 x LDC0 f32

    int tid  = threadIdx.x;
    int warp = tid >> 5;

    for (int i = tid; i < 128 * 128; i += 256) {
        int k = i >> 7, c = i & 127;
        sW[k * LDW0 + c] = __float2half(W[k * D + c]);
    }
    __syncthreads();

    int rg = warp >> 1;
    int cg = warp & 1;

    wmma::fragment<wmma::matrix_a, 16, 16, 16, __half, wmma::row_major> fa;
    wmma::fragment<wmma::matrix_b, 16, 16, 16, __half, wmma::row_major> fb;
    wmma::fragment<wmma::accumulator, 16, 16, 16, float> fc[4];

    for (int r0 = blockIdx.x * 64; r0 < n; r0 += gridDim.x * 64) {
        for (int i = tid; i < 64 * 128; i += 256) {
            int rr = i >> 7, c = i & 127;
            float v = (r0 + rr < n) ? g_pool[(size_t)(r0 + rr) * D + c] : 0.f;
            sX[rr * LDX + c] = __float2half(v);
        }
        __syncthreads();

#pragma unroll
        for (int j = 0; j < 4; j++) wmma::fill_fragment(fc[j], 0.f);

#pragma unroll
        for (int k = 0; k < 8; k++) {
            wmma::load_matrix_sync(fa, sX + (rg * 16) * LDX + k * 16, LDX);
#pragma unroll
            for (int j = 0; j < 4; j++) {
                wmma::load_matrix_sync(fb, sW + (k * 16) * LDW0 + cg * 64 + j * 16, LDW0);
                wmma::mma_sync(fc[j], fa, fb, fc[j]);
            }
        }

#pragma unroll
        for (int j = 0; j < 4; j++)
            wmma::store_matrix_sync(sC + (rg * 16) * LDC0 + cg * 64 + j * 16,
                                    fc[j], LDC0, wmma::mem_row_major);
        __syncthreads();

        for (int i = tid; i < 64 * 32; i += 256) {
            int rr = i >> 5;
            int c4 = (i & 31) * 4;
            int row = r0 + rr;
            if (row < n) {
                const float* crow = sC + rr * LDC0;
                float4 s = make_float4(crow[c4], crow[c4 + 1], crow[c4 + 2], crow[c4 + 3]);
                *(float4*)(g_static + (size_t)row * D + c4) = s;
                *(float4*)(g_h + (size_t)row * D + c4) =
                    make_float4(fmaxf(s.x, 0.f), fmaxf(s.y, 0.f),
                                fmaxf(s.z, 0.f), fmaxf(s.w, 0.f));
            }
        }
        __syncthreads();
    }
}

// ---------------------------------------------------------------------------
// wmma GEMM: [A | Yh] = h @ [W1 | W2] (R13-proven).
__global__ void __launch_bounds__(512) k_gemmAB(
    const float* __restrict__ W1, const float* __restrict__ W2, int n)
{
    extern __shared__ char smraw[];
    __half* sW = (__half*)smraw;                         // 128 x LDW fp16
    __half* sX = (__half*)(smraw + 128 * LDW * 2);       //  64 x LDX fp16
    float*  sC = (float*)(smraw + 128 * LDW * 2 + 64 * LDX * 2); // 64 x LDC f32

    int tid  = threadIdx.x;
    int warp = tid >> 5;

    for (int i = tid; i < 128 * 256; i += 512) {
        int k = i >> 8;
        int c = i & 255;
        float v = (c < 128) ? W1[k * D + c] : W2[k * D + (c - 128)];
        sW[k * LDW + c] = __float2half(v);
    }
    __syncthreads();

    int rg = warp >> 2;
    int cg = warp & 3;

    wmma::fragment<wmma::matrix_a, 16, 16, 16, __half, wmma::row_major> fa;
    wmma::fragment<wmma::matrix_b, 16, 16, 16, __half, wmma::row_major> fb;
    wmma::fragment<wmma::accumulator, 16, 16, 16, float> fc[4];

    for (int r0 = blockIdx.x * 64; r0 < n; r0 += gridDim.x * 64) {
        for (int i = tid; i < 64 * 128; i += 512) {
            int rr = i >> 7, c = i & 127;
            float v = (r0 + rr < n) ? g_h[(size_t)(r0 + rr) * D + c] : 0.f;
            sX[rr * LDX + c] = __float2half(v);
        }
        __syncthreads();

#pragma unroll
        for (int j = 0; j < 4; j++) wmma::fill_fragment(fc[j], 0.f);

#pragma unroll
        for (int k = 0; k < 8; k++) {
            wmma::load_matrix_sync(fa, sX + (rg * 16) * LDX + k * 16, LDX);
#pragma unroll
            for (int j = 0; j < 4; j++) {
                wmma::load_matrix_sync(fb, sW + (k * 16) * LDW + cg * 64 + j * 16, LDW);
                wmma::mma_sync(fc[j], fa, fb, fc[j]);
            }
        }

#pragma unroll
        for (int j = 0; j < 4; j++)
            wmma::store_matrix_sync(sC + (rg * 16) * LDC + cg * 64 + j * 16,
                                    fc[j], LDC, wmma::mem_row_major);
        __syncthreads();

        for (int i = tid; i < 64 * 32; i += 512) {
            int rr = i >> 5;
            int c4 = (i & 31) * 4;
            int row = r0 + rr;
            if (row < n) {
                const float* crow = sC + rr * LDC;
                float4 s = *(const float4*)(g_static + (size_t)row * D + c4);
                float4 a = make_float4(s.x + crow[c4],     s.y + crow[c4 + 1],
                                       s.z + crow[c4 + 2], s.w + crow[c4 + 3]);
                *(float4*)(g_A + (size_t)row * D + c4) = a;
                const float* crow2 = crow + 128;
                __half2 q0 = __floats2half2_rn(crow2[c4],     crow2[c4 + 1]);
                __half2 q1 = __floats2half2_rn(crow2[c4 + 2], crow2[c4 + 3]);
                uint2 pk;
                pk.x = *(unsigned int*)&q0;
                pk.y = *(unsigned int*)&q1;
                *(uint2*)(g_Yh + (size_t)row * D + c4) = pk;
            }
        }
        __syncthreads();
    }
}

// ---------------------------------------------------------------------------
// Fused n2n spmm + merge, unroll x8 (R14-proven).
__global__ void __launch_bounds__(256) k_spmm_merge(float* __restrict__ out, int n)
{
    int lane = threadIdx.x & 31;
    int gw   = (blockIdx.x * blockDim.x + threadIdx.x) >> 5;
    int nw   = (gridDim.x * blockDim.x) >> 5;
    float* dst = out ? out : g_h;   // device-side select (host g_h addr invalid)
    int col  = lane * 4;

    for (int d = gw; d < n; d += nw) {
        int j0 = g_off[1][d], j1 = g_off[1][d + 1];
        float4 acc0 = *(const float4*)(g_A + (size_t)d * D + col);
        float4 acc1 = make_float4(0.f, 0.f, 0.f, 0.f);
        float4 acc2 = make_float4(0.f, 0.f, 0.f, 0.f);
        float4 acc3 = make_float4(0.f, 0.f, 0.f, 0.f);

        int j = j0;
        for (; j + 8 <= j1; j += 8) {
            int s0 = __ldg(g_permB + j),     s1 = __ldg(g_permB + j + 1);
            int s2 = __ldg(g_permB + j + 2), s3 = __ldg(g_permB + j + 3);
            int s4 = __ldg(g_permB + j + 4), s5 = __ldg(g_permB + j + 5);
            int s6 = __ldg(g_permB + j + 6), s7 = __ldg(g_permB + j + 7);
            uint2 r0 = *(const uint2*)(g_Yh + (size_t)s0 * D + col);
            uint2 r1 = *(const uint2*)(g_Yh + (size_t)s1 * D + col);
            uint2 r2 = *(const uint2*)(g_Yh + (size_t)s2 * D + col);
            uint2 r3 = *(const uint2*)(g_Yh + (size_t)s3 * D + col);
            uint2 r4 = *(const uint2*)(g_Yh + (size_t)s4 * D + col);
            uint2 r5 = *(const uint2*)(g_Yh + (size_t)s5 * D + col);
            uint2 r6 = *(const uint2*)(g_Yh + (size_t)s6 * D + col);
            uint2 r7 = *(const uint2*)(g_Yh + (size_t)s7 * D + col);
            float2 fa, fb;
#define ACC(P, R) \
            fa = __half22float2(*(__half2*)&R.x); fb = __half22float2(*(__half2*)&R.y); \
            P.x += fa.x; P.y += fa.y; P.z += fb.x; P.w += fb.y;
            ACC(acc0, r0) ACC(acc1, r1) ACC(acc2, r2) ACC(acc3, r3)
            ACC(acc0, r4) ACC(acc1, r5) ACC(acc2, r6) ACC(acc3, r7)
        }
        for (; j + 4 <= j1; j += 4) {
            int s0 = __ldg(g_permB + j),     s1 = __ldg(g_permB + j + 1);
            int s2 = __ldg(g_permB + j + 2), s3 = __ldg(g_permB + j + 3);
            uint2 r0 = *(const uint2*)(g_Yh + (size_t)s0 * D + col);
            uint2 r1 = *(const uint2*)(g_Yh + (size_t)s1 * D + col);
            uint2 r2 = *(const uint2*)(g_Yh + (size_t)s2 * D + col);
            uint2 r3 = *(const uint2*)(g_Yh + (size_t)s3 * D + col);
            float2 fa, fb;
            ACC(acc0, r0) ACC(acc1, r1) ACC(acc2, r2) ACC(acc3, r3)
        }
        for (; j < j1; j++) {
            int s0 = __ldg(g_permB + j);
            uint2 r0 = *(const uint2*)(g_Yh + (size_t)s0 * D + col);
            float2 fa, fb;
            ACC(acc0, r0)
        }
#undef ACC
        float4 o;
        o.x = fmaxf(acc0.x + acc1.x + acc2.x + acc3.x, 0.f);
        o.y = fmaxf(acc0.y + acc1.y + acc2.y + acc3.y, 0.f);
        o.z = fmaxf(acc0.z + acc1.z + acc2.z + acc3.z, 0.f);
        o.w = fmaxf(acc0.w + acc1.w + acc2.w + acc3.w, 0.f);
        *(float4*)(dst + (size_t)d * D + col) = o;
    }
}

// ---------------------------------------------------------------------------
extern "C" void kernel_launch(void* const* d_in, const int* in_sizes, int n_in,
                              void* d_out, int out_size)
{
    const float* edge_feat = (const float*)d_in[0];
    const float* W_e2l     = (const float*)d_in[1];
    const float* W0        = (const float*)d_in[2];
    const float* W1s[3] = { (const float*)d_in[3], (const float*)d_in[5], (const float*)d_in[7] };
    const float* W2s[3] = { (const float*)d_in[4], (const float*)d_in[6], (const float*)d_in[8] };
    const int* e2n_dst  = (const int*)d_in[9];
    const int* edge_src = (const int*)d_in[10];
    const int* edge_dst = (const int*)d_in[11];

    int E = in_sizes[9];
    int n = out_size / D;
    int nchunk = (n + 255) / 256;

    const int smem_w0 = 128 * LDW0 * 2 + 64 * LDX * 2 + 64 * LDC0 * 4;       // ~86 KB
    const int smem_ab = 128 * LDW * 2 + 64 * LDX * 2 + 64 * LDC * 4;         // ~149 KB
    cudaFuncSetAttribute(k_gemm_w0, cudaFuncAttributeMaxDynamicSharedMemorySize, smem_w0);
    cudaFuncSetAttribute(k_gemmAB,  cudaFuncAttributeMaxDynamicSharedMemorySize, smem_ab);

    int node_blocks = (n + 7) / 8;     // warp per node
    int e4_blocks   = (E / 4 + 255) / 256;

    // --- CSR build ---
    k_zero_cnt<<<196, 256>>>(n);
    k_hist<<<e4_blocks, 256>>>(e2n_dst, edge_dst, E);
    dim3 sg(nchunk, 2);
    k_scan1<<<sg, 256>>>(n);
    k_scan2<<<1, 256>>>(n, nchunk);
    k_scan3<<<sg, 256>>>(n);
    k_fill<<<e4_blocks, 256>>>(e2n_dst, edge_dst, edge_src, E);

    // --- node pipeline ---
    k_edge_pool<<<node_blocks, 256>>>(edge_feat, W_e2l, n);
    k_gemm_w0<<<296, 256, smem_w0>>>(W0, n);

    for (int it = 0; it < 3; it++) {
        k_gemmAB<<<148, 512, smem_ab>>>(W1s[it], W2s[it], n);
        k_spmm_merge<<<node_blocks, 256>>>(it == 2 ? (float*)d_out : nullptr, n);
    }
}

// round 17
// speedup vs baseline: 2.0728x; 1.3975x over previous
#include <cuda_runtime.h>
#include <cuda_fp16.h>
#include <mma.h>

using namespace nvcuda;

#define D      128
#define EF     16
#define NMAX   50000
#define EMAX   1600000
#define NCHUNK_MAX 256   // ceil(NMAX/256) = 196 <= 256

typedef unsigned long long u64;

// wmma staging leading dims (all ldm are multiples of 16 bytes)
#define LDX 136      // fp16 X stage:    64 x 136
#define LDW 264      // fp16 W1|W2:     128 x 264
#define LDC 264      // fp32 C stage:    64 x 264
#define LDW0 136     // fp16 W0:        128 x 136
#define LDC0 136     // fp32 C stage:    64 x 136
#define LDE 24       // fp16 edge A tile: 16 x 24
#define LDR 20       // fp32 reduce tile: 16 x 20 (80B rows)

// ---------------- scratch (device globals; zero-init, no allocation) -------
__device__ __half g_poolh[NMAX * D];   // e2n pooled edge messages (fp16)
__device__ float  g_static[NMAX * D];  // e2n_pool @ W0 (pre-relu, fp32)
__device__ float  g_A[NMAX * D];       // static + h @ W1 (fp32)
__device__ __half g_Yh[NMAX * D];      // h @ W2 (fp16)
__device__ __half g_hh[NMAX * D];      // hidden state (fp16)

__device__ int g_cnt[2][NMAX];
__device__ int g_off[2][NMAX + 1];
__device__ int g_cur[2][NMAX];
__device__ int g_csum[2][NCHUNK_MAX];
__device__ int g_coff[2][NCHUNK_MAX];
__device__ int g_permA[EMAX];          // edge ids grouped by e2n_dst
__device__ int g_permB[EMAX];          // edge_src values grouped by edge_dst

// ---------------- CSR builders ---------------------------------------------
__global__ void k_hist(const int* __restrict__ e2n, const int* __restrict__ ndst, int E) {
    int E4 = E >> 2;
    int i = blockIdx.x * blockDim.x + threadIdx.x;
    int s = gridDim.x * blockDim.x;
    for (; i < E4; i += s) {
        int4 a = ((const int4*)e2n)[i];
        int4 b = ((const int4*)ndst)[i];
        atomicAdd(&g_cnt[0][a.x], 1); atomicAdd(&g_cnt[0][a.y], 1);
        atomicAdd(&g_cnt[0][a.z], 1); atomicAdd(&g_cnt[0][a.w], 1);
        atomicAdd(&g_cnt[1][b.x], 1); atomicAdd(&g_cnt[1][b.y], 1);
        atomicAdd(&g_cnt[1][b.z], 1); atomicAdd(&g_cnt[1][b.w], 1);
    }
    int t = E4 * 4 + (blockIdx.x * blockDim.x + threadIdx.x);
    if (t < E) {
        atomicAdd(&g_cnt[0][e2n[t]], 1);
        atomicAdd(&g_cnt[1][ndst[t]], 1);
    }
}

__global__ void k_scan1(int n) {
    __shared__ int sh[256];
    int a = blockIdx.y;
    int i = blockIdx.x * 256 + threadIdx.x;
    sh[threadIdx.x] = (i < n) ? g_cnt[a][i] : 0;
    __syncthreads();
    for (int o = 128; o > 0; o >>= 1) {
        if (threadIdx.x < o) sh[threadIdx.x] += sh[threadIdx.x + o];
        __syncthreads();
    }
    if (threadIdx.x == 0) g_csum[a][blockIdx.x] = sh[0];
}

__global__ void k_scan2(int n, int nchunk) {
    __shared__ int sh[256];
    for (int a = 0; a < 2; a++) {
        int v = (threadIdx.x < nchunk) ? g_csum[a][threadIdx.x] : 0;
        sh[threadIdx.x] = v;
        __syncthreads();
        for (int o = 1; o < 256; o <<= 1) {
            int t = (threadIdx.x >= o) ? sh[threadIdx.x - o] : 0;
            __syncthreads();
            sh[threadIdx.x] += t;
            __syncthreads();
        }
        if (threadIdx.x < nchunk) g_coff[a][threadIdx.x] = sh[threadIdx.x] - v;
        if (threadIdx.x == 255)   g_off[a][n] = sh[255];
        __syncthreads();
    }
}

// scan3 also resets g_cnt to 0 after its final read (replaces k_zero_cnt;
// device globals are zero-init, so every call sees cnt=0 deterministically).
__global__ void k_scan3(int n) {
    __shared__ int sh[256];
    int a = blockIdx.y;
    int i = blockIdx.x * 256 + threadIdx.x;
    int v = (i < n) ? g_cnt[a][i] : 0;
    sh[threadIdx.x] = v;
    __syncthreads();
    for (int o = 1; o < 256; o <<= 1) {
        int t = (threadIdx.x >= o) ? sh[threadIdx.x - o] : 0;
        __syncthreads();
        sh[threadIdx.x] += t;
        __syncthreads();
    }
    if (i < n) {
        int excl = g_coff[a][blockIdx.x] + sh[threadIdx.x] - v;
        g_off[a][i] = excl;
        g_cur[a][i] = excl;
        g_cnt[a][i] = 0;
    }
}

__global__ void k_fill(const int* __restrict__ e2n, const int* __restrict__ ndst,
                       const int* __restrict__ nsrc, int E) {
    int E4 = E >> 2;
    int i = blockIdx.x * blockDim.x + threadIdx.x;
    int s = gridDim.x * blockDim.x;
    for (; i < E4; i += s) {
        int4 a = ((const int4*)e2n)[i];
        int4 b = ((const int4*)ndst)[i];
        int4 c = ((const int4*)nsrc)[i];
        int base = i * 4;
        int pa0 = atomicAdd(&g_cur[0][a.x], 1);
        int pa1 = atomicAdd(&g_cur[0][a.y], 1);
        int pa2 = atomicAdd(&g_cur[0][a.z], 1);
        int pa3 = atomicAdd(&g_cur[0][a.w], 1);
        int pb0 = atomicAdd(&g_cur[1][b.x], 1);
        int pb1 = atomicAdd(&g_cur[1][b.y], 1);
        int pb2 = atomicAdd(&g_cur[1][b.z], 1);
        int pb3 = atomicAdd(&g_cur[1][b.w], 1);
        g_permA[pa0] = base;     g_permA[pa1] = base + 1;
        g_permA[pa2] = base + 2; g_permA[pa3] = base + 3;
        g_permB[pb0] = c.x; g_permB[pb1] = c.y;
        g_permB[pb2] = c.z; g_permB[pb3] = c.w;
    }
    int t = E4 * 4 + (blockIdx.x * blockDim.x + threadIdx.x);
    if (t < E) {
        int pa = atomicAdd(&g_cur[0][e2n[t]], 1);
        g_permA[pa] = t;
        int pb = atomicAdd(&g_cur[1][ndst[t]], 1);
        g_permB[pb] = nsrc[t];
    }
}

// ---------------------------------------------------------------------------
// wmma e2n pool: poolh[d] = fp16( sum_{e in N(d)} relu(ef[e] @ We) ).
// Zero-fragment C operand avoids per-chunk fill_fragment.
__global__ void __launch_bounds__(256) k_edge_pool(
    const float* __restrict__ ef, const float* __restrict__ We, int n)
{
    __shared__ __half sWe[EF * LDW0];          // 16 x 136 fp16
    __shared__ __half sA[8][16 * LDE];         // per-warp edge tile
    __shared__ float  sR[8][16 * LDR];         // per-warp reduce tile

    int tid  = threadIdx.x;
    int warp = tid >> 5;
    int lane = tid & 31;

    for (int i = tid; i < EF * D; i += 256) {
        int k = i >> 7, c = i & 127;
        sWe[k * LDW0 + c] = __float2half(We[i]);
    }
    __syncthreads();

    wmma::fragment<wmma::matrix_a, 16, 16, 16, __half, wmma::row_major> fa;
    wmma::fragment<wmma::matrix_b, 16, 16, 16, __half, wmma::row_major> fB[8];
#pragma unroll
    for (int j = 0; j < 8; j++)
        wmma::load_matrix_sync(fB[j], sWe + j * 16, LDW0);

    wmma::fragment<wmma::accumulator, 16, 16, 16, float> pool[8], work, fzero;
    wmma::fill_fragment(fzero, 0.f);   // constant zero C operand

    int gw = blockIdx.x * 8 + warp;
    int nw = gridDim.x * 8;
    int slot = lane >> 1;
    int half_ = lane & 1;

    for (int d = gw; d < n; d += nw) {
        int j0 = g_off[0][d], j1 = g_off[0][d + 1];
#pragma unroll
        for (int j = 0; j < 8; j++) wmma::fill_fragment(pool[j], 0.f);

        for (int base = j0; base < j1; base += 16) {
            uint4 pk = make_uint4(0u, 0u, 0u, 0u);
            int er = base + slot;
            if (er < j1) {
                int e = g_permA[er];
                const float4* p = (const float4*)(ef + (size_t)e * EF + half_ * 8);
                float4 v0 = p[0], v1 = p[1];
                __half2 h0 = __floats2half2_rn(v0.x, v0.y);
                __half2 h1 = __floats2half2_rn(v0.z, v0.w);
                __half2 h2 = __floats2half2_rn(v1.x, v1.y);
                __half2 h3 = __floats2half2_rn(v1.z, v1.w);
                pk.x = *(unsigned int*)&h0;
                pk.y = *(unsigned int*)&h1;
                pk.z = *(unsigned int*)&h2;
                pk.w = *(unsigned int*)&h3;
            }
            *(uint4*)(&sA[warp][slot * LDE + half_ * 8]) = pk;
            __syncwarp();

            wmma::load_matrix_sync(fa, sA[warp], LDE);
#pragma unroll
            for (int j = 0; j < 8; j++) {
                wmma::mma_sync(work, fa, fB[j], fzero);
#pragma unroll
                for (int t = 0; t < work.num_elements; t++)
                    pool[j].x[t] += fmaxf(work.x[t], 0.f);
            }
            __syncwarp();
        }

#pragma unroll
        for (int j = 0; j < 8; j++) {
            wmma::store_matrix_sync(sR[warp], pool[j], LDR, wmma::mem_row_major);
            __syncwarp();
            if (lane < 16) {
                float s = 0.f;
#pragma unroll
                for (int r = 0; r < 16; r++) s += sR[warp][r * LDR + lane];
                g_poolh[(size_t)d * D + j * 16 + lane] = __float2half(s);
            }
            __syncwarp();
        }
    }
}

// ---------------------------------------------------------------------------
// wmma W0 GEMM: static = poolh @ W0 ; hh = fp16(relu(static)).
// Staging is a pure uint4 copy (poolh already fp16).
__global__ void __launch_bounds__(256) k_gemm_w0(const float* __restrict__ W, int n)
{
    extern __shared__ char smraw[];
    __half* sW = (__half*)smraw;                           // 128 x LDW0 fp16
    __half* sX = (__half*)(smraw + 128 * LDW0 * 2);        //  64 x LDX  fp16
    float*  sC = (float*)(smraw + 128 * LDW0 * 2 + 64 * LDX * 2); // 64 x LDC0 f32

    int tid  = threadIdx.x;
    int warp = tid >> 5;

    for (int i = tid; i < 128 * 128; i += 256) {
        int k = i >> 7, c = i & 127;
        sW[k * LDW0 + c] = __float2half(W[k * D + c]);
    }
    __syncthreads();

    int rg = warp >> 1;
    int cg = warp & 1;

    wmma::fragment<wmma::matrix_a, 16, 16, 16, __half, wmma::row_major> fa;
    wmma::fragment<wmma::matrix_b, 16, 16, 16, __half, wmma::row_major> fb;
    wmma::fragment<wmma::accumulator, 16, 16, 16, float> fc[4];

    for (int r0 = blockIdx.x * 64; r0 < n; r0 += gridDim.x * 64) {
        for (int i = tid; i < 64 * 16; i += 256) {      // 16 uint4 per row of 128 halves
            int rr = i >> 4, c8 = (i & 15) * 8;
            uint4 v = make_uint4(0u, 0u, 0u, 0u);
            if (r0 + rr < n)
                v = *(const uint4*)(g_poolh + (size_t)(r0 + rr) * D + c8);
            *(uint4*)(sX + rr * LDX + c8) = v;
        }
        __syncthreads();

#pragma unroll
        for (int j = 0; j < 4; j++) wmma::fill_fragment(fc[j], 0.f);

#pragma unroll
        for (int k = 0; k < 8; k++) {
            wmma::load_matrix_sync(fa, sX + (rg * 16) * LDX + k * 16, LDX);
#pragma unroll
            for (int j = 0; j < 4; j++) {
                wmma::load_matrix_sync(fb, sW + (k * 16) * LDW0 + cg * 64 + j * 16, LDW0);
                wmma::mma_sync(fc[j], fa, fb, fc[j]);
            }
        }

#pragma unroll
        for (int j = 0; j < 4; j++)
            wmma::store_matrix_sync(sC + (rg * 16) * LDC0 + cg * 64 + j * 16,
                                    fc[j], LDC0, wmma::mem_row_major);
        __syncthreads();

        for (int i = tid; i < 64 * 32; i += 256) {
            int rr = i >> 5;
            int c4 = (i & 31) * 4;
            int row = r0 + rr;
            if (row < n) {
                const float* crow = sC + rr * LDC0;
                float4 s = make_float4(crow[c4], crow[c4 + 1], crow[c4 + 2], crow[c4 + 3]);
                *(float4*)(g_static + (size_t)row * D + c4) = s;
                __half2 q0 = __floats2half2_rn(fmaxf(s.x, 0.f), fmaxf(s.y, 0.f));
                __half2 q1 = __floats2half2_rn(fmaxf(s.z, 0.f), fmaxf(s.w, 0.f));
                uint2 pk;
                pk.x = *(unsigned int*)&q0;
                pk.y = *(unsigned int*)&q1;
                *(uint2*)(g_hh + (size_t)row * D + c4) = pk;
            }
        }
        __syncthreads();
    }
}

// ---------------------------------------------------------------------------
// wmma GEMM: [A | Yh] = hh @ [W1 | W2]. Staging is a uint4 copy.
__global__ void __launch_bounds__(512) k_gemmAB(
    const float* __restrict__ W1, const float* __restrict__ W2, int n)
{
    extern __shared__ char smraw[];
    __half* sW = (__half*)smraw;                         // 128 x LDW fp16
    __half* sX = (__half*)(smraw + 128 * LDW * 2);       //  64 x LDX fp16
    float*  sC = (float*)(smraw + 128 * LDW * 2 + 64 * LDX * 2); // 64 x LDC f32

    int tid  = threadIdx.x;
    int warp = tid >> 5;

    for (int i = tid; i < 128 * 256; i += 512) {
        int k = i >> 8;
        int c = i & 255;
        float v = (c < 128) ? W1[k * D + c] : W2[k * D + (c - 128)];
        sW[k * LDW + c] = __float2half(v);
    }
    __syncthreads();

    int rg = warp >> 2;
    int cg = warp & 3;

    wmma::fragment<wmma::matrix_a, 16, 16, 16, __half, wmma::row_major> fa;
    wmma::fragment<wmma::matrix_b, 16, 16, 16, __half, wmma::row_major> fb;
    wmma::fragment<wmma::accumulator, 16, 16, 16, float> fc[4];

    for (int r0 = blockIdx.x * 64; r0 < n; r0 += gridDim.x * 64) {
        for (int i = tid; i < 64 * 16; i += 512) {
            int rr = i >> 4, c8 = (i & 15) * 8;
            uint4 v = make_uint4(0u, 0u, 0u, 0u);
            if (r0 + rr < n)
                v = *(const uint4*)(g_hh + (size_t)(r0 + rr) * D + c8);
            *(uint4*)(sX + rr * LDX + c8) = v;
        }
        __syncthreads();

#pragma unroll
        for (int j = 0; j < 4; j++) wmma::fill_fragment(fc[j], 0.f);

#pragma unroll
        for (int k = 0; k < 8; k++) {
            wmma::load_matrix_sync(fa, sX + (rg * 16) * LDX + k * 16, LDX);
#pragma unroll
            for (int j = 0; j < 4; j++) {
                wmma::load_matrix_sync(fb, sW + (k * 16) * LDW + cg * 64 + j * 16, LDW);
                wmma::mma_sync(fc[j], fa, fb, fc[j]);
            }
        }

#pragma unroll
        for (int j = 0; j < 4; j++)
            wmma::store_matrix_sync(sC + (rg * 16) * LDC + cg * 64 + j * 16,
                                    fc[j], LDC, wmma::mem_row_major);
        __syncthreads();

        for (int i = tid; i < 64 * 32; i += 512) {
            int rr = i >> 5;
            int c4 = (i & 31) * 4;
            int row = r0 + rr;
            if (row < n) {
                const float* crow = sC + rr * LDC;
                float4 s = *(const float4*)(g_static + (size_t)row * D + c4);
                float4 a = make_float4(s.x + crow[c4],     s.y + crow[c4 + 1],
                                       s.z + crow[c4 + 2], s.w + crow[c4 + 3]);
                *(float4*)(g_A + (size_t)row * D + c4) = a;
                const float* crow2 = crow + 128;
                __half2 q0 = __floats2half2_rn(crow2[c4],     crow2[c4 + 1]);
                __half2 q1 = __floats2half2_rn(crow2[c4 + 2], crow2[c4 + 3]);
                uint2 pk;
                pk.x = *(unsigned int*)&q0;
                pk.y = *(unsigned int*)&q1;
                *(uint2*)(g_Yh + (size_t)row * D + c4) = pk;
            }
        }
        __syncthreads();
    }
}

// ---------------------------------------------------------------------------
// Fused n2n spmm + merge, unroll x8. Intermediate output -> g_hh (fp16),
// final output -> out (fp32).
__global__ void __launch_bounds__(256) k_spmm_merge(float* __restrict__ out, int n)
{
    int lane = threadIdx.x & 31;
    int gw   = (blockIdx.x * blockDim.x + threadIdx.x) >> 5;
    int nw   = (gridDim.x * blockDim.x) >> 5;
    int col  = lane * 4;

    for (int d = gw; d < n; d += nw) {
        int j0 = g_off[1][d], j1 = g_off[1][d + 1];
        float4 acc0 = *(const float4*)(g_A + (size_t)d * D + col);
        float4 acc1 = make_float4(0.f, 0.f, 0.f, 0.f);
        float4 acc2 = make_float4(0.f, 0.f, 0.f, 0.f);
        float4 acc3 = make_float4(0.f, 0.f, 0.f, 0.f);

        int j = j0;
        for (; j + 8 <= j1; j += 8) {
            int s0 = __ldg(g_permB + j),     s1 = __ldg(g_permB + j + 1);
            int s2 = __ldg(g_permB + j + 2), s3 = __ldg(g_permB + j + 3);
            int s4 = __ldg(g_permB + j + 4), s5 = __ldg(g_permB + j + 5);
            int s6 = __ldg(g_permB + j + 6), s7 = __ldg(g_permB + j + 7);
            uint2 r0 = *(const uint2*)(g_Yh + (size_t)s0 * D + col);
            uint2 r1 = *(const uint2*)(g_Yh + (size_t)s1 * D + col);
            uint2 r2 = *(const uint2*)(g_Yh + (size_t)s2 * D + col);
            uint2 r3 = *(const uint2*)(g_Yh + (size_t)s3 * D + col);
            uint2 r4 = *(const uint2*)(g_Yh + (size_t)s4 * D + col);
            uint2 r5 = *(const uint2*)(g_Yh + (size_t)s5 * D + col);
            uint2 r6 = *(const uint2*)(g_Yh + (size_t)s6 * D + col);
            uint2 r7 = *(const uint2*)(g_Yh + (size_t)s7 * D + col);
            float2 fa, fb;
#define ACC(P, R) \
            fa = __half22float2(*(__half2*)&R.x); fb = __half22float2(*(__half2*)&R.y); \
            P.x += fa.x; P.y += fa.y; P.z += fb.x; P.w += fb.y;
            ACC(acc0, r0) ACC(acc1, r1) ACC(acc2, r2) ACC(acc3, r3)
            ACC(acc0, r4) ACC(acc1, r5) ACC(acc2, r6) ACC(acc3, r7)
        }
        for (; j + 4 <= j1; j += 4) {
            int s0 = __ldg(g_permB + j),     s1 = __ldg(g_permB + j + 1);
            int s2 = __ldg(g_permB + j + 2), s3 = __ldg(g_permB + j + 3);
            uint2 r0 = *(const uint2*)(g_Yh + (size_t)s0 * D + col);
            uint2 r1 = *(const uint2*)(g_Yh + (size_t)s1 * D + col);
            uint2 r2 = *(const uint2*)(g_Yh + (size_t)s2 * D + col);
            uint2 r3 = *(const uint2*)(g_Yh + (size_t)s3 * D + col);
            float2 fa, fb;
            ACC(acc0, r0) ACC(acc1, r1) ACC(acc2, r2) ACC(acc3, r3)
        }
        for (; j < j1; j++) {
            int s0 = __ldg(g_permB + j);
            uint2 r0 = *(const uint2*)(g_Yh + (size_t)s0 * D + col);
            float2 fa, fb;
            ACC(acc0, r0)
        }
#undef ACC
        float4 o;
        o.x = fmaxf(acc0.x + acc1.x + acc2.x + acc3.x, 0.f);
        o.y = fmaxf(acc0.y + acc1.y + acc2.y + acc3.y, 0.f);
        o.z = fmaxf(acc0.z + acc1.z + acc2.z + acc3.z, 0.f);
        o.w = fmaxf(acc0.w + acc1.w + acc2.w + acc3.w, 0.f);
        if (out) {
            *(float4*)(out + (size_t)d * D + col) = o;
        } else {
            __half2 q0 = __floats2half2_rn(o.x, o.y);
            __half2 q1 = __floats2half2_rn(o.z, o.w);
            uint2 pk;
            pk.x = *(unsigned int*)&q0;
            pk.y = *(unsigned int*)&q1;
            *(uint2*)(g_hh + (size_t)d * D + col) = pk;
        }
    }
}

// ---------------------------------------------------------------------------
extern "C" void kernel_launch(void* const* d_in, const int* in_sizes, int n_in,
                              void* d_out, int out_size)
{
    const float* edge_feat = (const float*)d_in[0];
    const float* W_e2l     = (const float*)d_in[1];
    const float* W0        = (const float*)d_in[2];
    const float* W1s[3] = { (const float*)d_in[3], (const float*)d_in[5], (const float*)d_in[7] };
    const float* W2s[3] = { (const float*)d_in[4], (const float*)d_in[6], (const float*)d_in[8] };
    const int* e2n_dst  = (const int*)d_in[9];
    const int* edge_src = (const int*)d_in[10];
    const int* edge_dst = (const int*)d_in[11];

    int E = in_sizes[9];
    int n = out_size / D;
    int nchunk = (n + 255) / 256;

    const int smem_w0 = 128 * LDW0 * 2 + 64 * LDX * 2 + 64 * LDC0 * 4;       // ~86 KB
    const int smem_ab = 128 * LDW * 2 + 64 * LDX * 2 + 64 * LDC * 4;         // ~149 KB
    cudaFuncSetAttribute(k_gemm_w0, cudaFuncAttributeMaxDynamicSharedMemorySize, smem_w0);
    cudaFuncSetAttribute(k_gemmAB,  cudaFuncAttributeMaxDynamicSharedMemorySize, smem_ab);

    int node_blocks = (n + 7) / 8;     // warp per node
    int e4_blocks   = (E / 4 + 255) / 256;

    // --- CSR build (g_cnt arrives zeroed: zero-init first call, scan3 resets) ---
    k_hist<<<e4_blocks, 256>>>(e2n_dst, edge_dst, E);
    dim3 sg(nchunk, 2);
    k_scan1<<<sg, 256>>>(n);
    k_scan2<<<1, 256>>>(n, nchunk);
    k_scan3<<<sg, 256>>>(n);
    k_fill<<<e4_blocks, 256>>>(e2n_dst, edge_dst, edge_src, E);

    // --- node pipeline ---
    k_edge_pool<<<node_blocks, 256>>>(edge_feat, W_e2l, n);
    k_gemm_w0<<<296, 256, smem_w0>>>(W0, n);

    for (int it = 0; it < 3; it++) {
        k_gemmAB<<<148, 512, smem_ab>>>(W1s[it], W2s[it], n);
        k_spmm_merge<<<node_blocks, 256>>>(it == 2 ? (float*)d_out : nullptr, n);
    }
}